// round 4
// baseline (speedup 1.0000x reference)
#include <cuda_runtime.h>

// ============================================================================
// NystromAttention — fp32 baseline
//   b=4, n=4096, dim=1024, H=16, DH=64, M=256 landmarks, 6 MP iters, K=13 conv
// All big ops are a single tiled SGEMM (128x64x16 tile, 8x4 per thread),
// batched over b*h via gridDim.z. Everything runs on the default stream and
// is graph-capturable (kernel launches only, no alloc, no sync).
// ============================================================================

// ---------------- scratch (device globals; no allocation allowed) ----------
__device__ float g_qkv  [50331648];  // [16384, 3072]
__device__ float g_Q    [16777216];  // [b,h,n,d] scaled
__device__ float g_K    [16777216];
__device__ float g_V    [16777216];
__device__ float g_ql   [1048576];   // [bh, 256, 64]
__device__ float g_kl   [1048576];
__device__ float g_attn1[67108864];  // [bh, 4096, 256]
__device__ float g_attn3[67108864];  // [bh, 256, 4096]
__device__ float g_attn2[4194304];   // [bh, 256, 256]
__device__ float g_z0   [4194304];
__device__ float g_z1   [4194304];
__device__ float g_az   [4194304];
__device__ float g_t2   [4194304];
__device__ float g_t4   [4194304];
__device__ float g_a3v  [1048576];   // [bh, 256, 64]
__device__ float g_tmp2 [1048576];   // [bh, 256, 64]
__device__ float g_out  [16777216];  // [b,h,n,d]
__device__ float g_out2 [16777216];  // after conv residual
__device__ float g_outT [16777216];  // [b,n,1024]
__device__ unsigned int g_m1, g_m2;  // global maxes for MP init

// ---------------- SGEMM ----------------------------------------------------
// C = outScale * A @ Beff (+ bias), Beff = B (NN), B^T (NT), or alpha*I - B.
// Tiles: BM=128, BN=64, BK=16; 256 threads; thread tile 8x4.
// All problem dims here are exact multiples of the tiles — no bounds checks.
template<bool TRANSB, bool AIM, bool BIAS>
__global__ __launch_bounds__(256)
void sgemm(const float* __restrict__ A, const float* __restrict__ B,
           float* __restrict__ C, int Kdim, int lda, int ldb, int ldc,
           long long sA, long long sB, long long sC,
           float alpha, float outScale, const float* __restrict__ bias)
{
    constexpr int BM = 128, BN = 64, BK = 16;
    __shared__ float As[BK][BM];
    __shared__ float Bs[BK][BN + 4];

    const float* Ab = A + (long long)blockIdx.z * sA;
    const float* Bb = B + (long long)blockIdx.z * sB;
    float*       Cb = C + (long long)blockIdx.z * sC;

    const int row0 = blockIdx.y * BM;
    const int col0 = blockIdx.x * BN;
    const int t  = threadIdx.x;
    const int tx = t & 15;       // 16 col groups of 4
    const int ty = t >> 4;       // 16 row groups of 8

    float acc[8][4];
    #pragma unroll
    for (int i = 0; i < 8; i++)
        #pragma unroll
        for (int j = 0; j < 4; j++) acc[i][j] = 0.f;

    for (int k0 = 0; k0 < Kdim; k0 += BK) {
        // ---- load A tile (128 x 16), transposed into As[k][m]
        #pragma unroll
        for (int ld = 0; ld < 2; ld++) {
            int idx = t + ld * 256;          // 0..511
            int r   = idx >> 2;              // 0..127
            int kq  = (idx & 3) << 2;        // 0,4,8,12
            float4 av = *reinterpret_cast<const float4*>(
                Ab + (long long)(row0 + r) * lda + k0 + kq);
            As[kq + 0][r] = av.x; As[kq + 1][r] = av.y;
            As[kq + 2][r] = av.z; As[kq + 3][r] = av.w;
        }
        // ---- load B tile into Bs[k][n]
        if (!TRANSB) {
            int r  = t >> 4;                 // 0..15 (k)
            int cq = (t & 15) << 2;          // 0..60 (n)
            float4 bv = *reinterpret_cast<const float4*>(
                Bb + (long long)(k0 + r) * ldb + col0 + cq);
            if (AIM) {
                int gk = k0 + r, gj = col0 + cq;
                bv.x = ((gk == gj    ) ? alpha : 0.f) - bv.x;
                bv.y = ((gk == gj + 1) ? alpha : 0.f) - bv.y;
                bv.z = ((gk == gj + 2) ? alpha : 0.f) - bv.z;
                bv.w = ((gk == gj + 3) ? alpha : 0.f) - bv.w;
            }
            *reinterpret_cast<float4*>(&Bs[r][cq]) = bv;
        } else {
            int j  = t >> 2;                 // 0..63 (n)
            int kq = (t & 3) << 2;           // 0,4,8,12
            float4 bv = *reinterpret_cast<const float4*>(
                Bb + (long long)(col0 + j) * ldb + k0 + kq);
            Bs[kq + 0][j] = bv.x; Bs[kq + 1][j] = bv.y;
            Bs[kq + 2][j] = bv.z; Bs[kq + 3][j] = bv.w;
        }
        __syncthreads();

        #pragma unroll
        for (int kk = 0; kk < BK; kk++) {
            float4 a0 = *reinterpret_cast<const float4*>(&As[kk][ty * 8]);
            float4 a1 = *reinterpret_cast<const float4*>(&As[kk][ty * 8 + 4]);
            float4 b0 = *reinterpret_cast<const float4*>(&Bs[kk][tx * 4]);
            float ar[8] = {a0.x, a0.y, a0.z, a0.w, a1.x, a1.y, a1.z, a1.w};
            float br[4] = {b0.x, b0.y, b0.z, b0.w};
            #pragma unroll
            for (int i = 0; i < 8; i++)
                #pragma unroll
                for (int j = 0; j < 4; j++)
                    acc[i][j] = fmaf(ar[i], br[j], acc[i][j]);
        }
        __syncthreads();
    }

    float bb[4] = {0.f, 0.f, 0.f, 0.f};
    if (BIAS) {
        #pragma unroll
        for (int j = 0; j < 4; j++) bb[j] = bias[col0 + tx * 4 + j];
    }
    #pragma unroll
    for (int i = 0; i < 8; i++) {
        float4 o;
        o.x = acc[i][0] * outScale + bb[0];
        o.y = acc[i][1] * outScale + bb[1];
        o.z = acc[i][2] * outScale + bb[2];
        o.w = acc[i][3] * outScale + bb[3];
        *reinterpret_cast<float4*>(
            Cb + (long long)(row0 + ty * 8 + i) * ldc + col0 + tx * 4) = o;
    }
}

// ---------------- elementwise / reductions ---------------------------------
// index layout for [b,h,n,d]: i = ((b*16+h)*4096+n)*64+d
__global__ void split_qkv_kernel(const float* __restrict__ qkv,
                                 float* __restrict__ Q, float* __restrict__ K,
                                 float* __restrict__ V)
{
    long long i = (long long)blockIdx.x * 256 + threadIdx.x;   // < 16777216
    int d = (int)(i & 63);
    int n = (int)((i >> 6) & 4095);
    int h = (int)((i >> 18) & 15);
    int b = (int)(i >> 22);
    long long src = ((long long)(b * 4096 + n)) * 3072 + h * 64 + d;
    Q[i] = qkv[src] * 0.125f;            // DH^-0.5 = 1/8
    K[i] = qkv[src + 1024];
    V[i] = qkv[src + 2048];
}

__global__ void landmarks_kernel(const float* __restrict__ Q,
                                 const float* __restrict__ K,
                                 float* __restrict__ ql, float* __restrict__ kl)
{
    int i = blockIdx.x * 256 + threadIdx.x;       // < 1048576  [bh,m,d]
    int d = i & 63;
    int m = (i >> 6) & 255;
    int bh = i >> 14;
    long long base = ((long long)bh * 4096 + m * 16) * 64 + d;
    float sq = 0.f, sk = 0.f;
    #pragma unroll
    for (int j = 0; j < 16; j++) {
        sq += Q[base + j * 64];
        sk += K[base + j * 64];
    }
    ql[i] = sq * 0.0625f;
    kl[i] = sk * 0.0625f;
}

// one warp per row of 256, in-place
__global__ void softmax256_kernel(float* __restrict__ data, int rows)
{
    int gw   = (int)((blockIdx.x * (long long)blockDim.x + threadIdx.x) >> 5);
    int lane = threadIdx.x & 31;
    if (gw >= rows) return;
    float* p = data + (long long)gw * 256;
    float v[8];
    float mx = -1e30f;
    #pragma unroll
    for (int i = 0; i < 8; i++) { v[i] = p[lane + 32 * i]; mx = fmaxf(mx, v[i]); }
    #pragma unroll
    for (int o = 16; o > 0; o >>= 1) mx = fmaxf(mx, __shfl_xor_sync(0xffffffffu, mx, o));
    float s = 0.f;
    #pragma unroll
    for (int i = 0; i < 8; i++) { v[i] = expf(v[i] - mx); s += v[i]; }
    #pragma unroll
    for (int o = 16; o > 0; o >>= 1) s += __shfl_xor_sync(0xffffffffu, s, o);
    float inv = 1.f / s;
    #pragma unroll
    for (int i = 0; i < 8; i++) p[lane + 32 * i] = v[i] * inv;
}

// one block (256 thr) per row of 4096, in-place
__global__ void softmax4096_kernel(float* __restrict__ data)
{
    float* p = data + (long long)blockIdx.x * 4096;
    int t = threadIdx.x;
    float v[16];
    float mx = -1e30f;
    #pragma unroll
    for (int i = 0; i < 16; i++) { v[i] = p[t + 256 * i]; mx = fmaxf(mx, v[i]); }
    __shared__ float red[256];
    red[t] = mx; __syncthreads();
    for (int s = 128; s > 0; s >>= 1) {
        if (t < s) red[t] = fmaxf(red[t], red[t + s]);
        __syncthreads();
    }
    mx = red[0]; __syncthreads();
    float sum = 0.f;
    #pragma unroll
    for (int i = 0; i < 16; i++) { v[i] = expf(v[i] - mx); sum += v[i]; }
    red[t] = sum; __syncthreads();
    for (int s = 128; s > 0; s >>= 1) {
        if (t < s) red[t] += red[t + s];
        __syncthreads();
    }
    float inv = 1.f / red[0];
    #pragma unroll
    for (int i = 0; i < 16; i++) p[t + 256 * i] = v[i] * inv;
}

__global__ void mp_reset_kernel() { g_m1 = 0u; g_m2 = 0u; }

// global max of row-sums and column-sums of |attn2| (per reference: jnp.max
// with no axis = max over ALL of [b,h,m,m])
__global__ void mp_reduce_kernel(const float* __restrict__ a)
{
    int bh = blockIdx.x;
    int j  = threadIdx.x;
    const float* p = a + (long long)bh * 65536;
    float rs = 0.f, cs = 0.f;
    for (int i = 0; i < 256; i++) {
        rs += fabsf(p[j * 256 + i]);   // row-sum of row j   (axis -1)
        cs += fabsf(p[i * 256 + j]);   // col-sum of col j   (axis -2)
    }
    __shared__ float r1[256], r2[256];
    r1[j] = rs; r2[j] = cs; __syncthreads();
    for (int s = 128; s > 0; s >>= 1) {
        if (j < s) { r1[j] = fmaxf(r1[j], r1[j + s]); r2[j] = fmaxf(r2[j], r2[j + s]); }
        __syncthreads();
    }
    if (j == 0) {
        atomicMax(&g_m1, __float_as_uint(r1[0]));
        atomicMax(&g_m2, __float_as_uint(r2[0]));
    }
}

// z0 = a^T / (max_rowsum * max_colsum)
__global__ void mp_init_kernel(const float* __restrict__ a, float* __restrict__ z)
{
    long long i = (long long)blockIdx.x * 256 + threadIdx.x;  // < 4194304
    int col = (int)(i & 255);
    int row = (int)((i >> 8) & 255);
    long long bh = i >> 16;
    float denom = __uint_as_float(g_m1) * __uint_as_float(g_m2);
    z[i] = a[bh * 65536 + (long long)col * 256 + row] / denom;
}

// depthwise residual conv over sequence dim (K=13, pad 6) + residual add
__global__ void conv_kernel(const float* __restrict__ src,
                            const float* __restrict__ w,   // [16,13]
                            float* __restrict__ dst)
{
    long long i = (long long)blockIdx.x * 256 + threadIdx.x;  // < 16777216
    int n = (int)((i >> 6) & 4095);
    int h = (int)((i >> 18) & 15);
    float r = 0.f;
    #pragma unroll
    for (int tt = 0; tt < 13; tt++) {
        int nn = n + tt - 6;
        if (nn >= 0 && nn < 4096)
            r += w[h * 13 + tt] * src[i + (long long)(tt - 6) * 64];
    }
    dst[i] = src[i] + r;
}

// [b,h,n,d] -> [b,n,h*64+d]
__global__ void to_bnd_kernel(const float* __restrict__ src, float* __restrict__ dst)
{
    long long i = (long long)blockIdx.x * 256 + threadIdx.x;  // < 16777216
    int d  = (int)(i & 63);
    int h  = (int)((i >> 6) & 15);
    int nn = (int)((i >> 10) & 4095);
    int b  = (int)(i >> 22);
    dst[i] = src[(((long long)b * 16 + h) * 4096 + nn) * 64 + d];
}

// ---------------- launch ----------------------------------------------------
extern "C" void kernel_launch(void* const* d_in, const int* in_sizes, int n_in,
                              void* d_out, int out_size)
{
    (void)in_sizes; (void)n_in; (void)out_size;
    const float* x      = (const float*)d_in[0];
    const float* w_qkv  = (const float*)d_in[1];
    const float* w_conv = (const float*)d_in[2];
    const float* w_fc   = (const float*)d_in[3];
    const float* b_fc   = (const float*)d_in[4];
    float* dout = (float*)d_out;

    void* vp;
    #define SYMP(nm) float* nm##_p; cudaGetSymbolAddress(&vp, nm); nm##_p = (float*)vp;
    SYMP(g_qkv)  SYMP(g_Q)    SYMP(g_K)    SYMP(g_V)
    SYMP(g_ql)   SYMP(g_kl)
    SYMP(g_attn1) SYMP(g_attn3) SYMP(g_attn2)
    SYMP(g_z0)   SYMP(g_z1)   SYMP(g_az)   SYMP(g_t2) SYMP(g_t4)
    SYMP(g_a3v)  SYMP(g_tmp2)
    SYMP(g_out)  SYMP(g_out2) SYMP(g_outT)
    #undef SYMP

    // 1. qkv = x @ w_qkv   [16384,1024]@[1024,3072]
    sgemm<false,false,false><<<dim3(48, 128, 1), 256>>>(
        x, w_qkv, g_qkv_p, 1024, 1024, 3072, 3072, 0, 0, 0, 0.f, 1.f, nullptr);

    // 2. split + scale
    split_qkv_kernel<<<65536, 256>>>(g_qkv_p, g_Q_p, g_K_p, g_V_p);

    // 3. landmarks (means of 16 tokens)
    landmarks_kernel<<<4096, 256>>>(g_Q_p, g_K_p, g_ql_p, g_kl_p);

    // 4. sim1 = Q @ kl^T   [4096,64]@[256,64]^T  (batch 64)
    sgemm<true,false,false><<<dim3(4, 32, 64), 256>>>(
        g_Q_p, g_kl_p, g_attn1_p, 64, 64, 64, 256,
        262144LL, 16384LL, 1048576LL, 0.f, 1.f, nullptr);

    // 5. sim2 = ql @ kl^T  [256,64]@[256,64]^T
    sgemm<true,false,false><<<dim3(4, 2, 64), 256>>>(
        g_ql_p, g_kl_p, g_attn2_p, 64, 64, 64, 256,
        16384LL, 16384LL, 65536LL, 0.f, 1.f, nullptr);

    // 6. sim3 = ql @ K^T   [256,64]@[4096,64]^T
    sgemm<true,false,false><<<dim3(64, 2, 64), 256>>>(
        g_ql_p, g_K_p, g_attn3_p, 64, 64, 64, 4096,
        16384LL, 262144LL, 1048576LL, 0.f, 1.f, nullptr);

    // 7. softmaxes (in place)
    softmax256_kernel<<<32768, 256>>>(g_attn1_p, 262144);
    softmax256_kernel<<<2048, 256>>>(g_attn2_p, 16384);
    softmax4096_kernel<<<16384, 256>>>(g_attn3_p);

    // 8. Moore-Penrose init: z0 = attn2^T / (max(rowsum)*max(colsum))
    mp_reset_kernel<<<1, 1>>>();
    mp_reduce_kernel<<<64, 256>>>(g_attn2_p);
    mp_init_kernel<<<16384, 256>>>(g_attn2_p, g_z0_p);

    // 9. 6 Newton-Schulz iterations (batched 256^3 GEMMs)
    float* zin = g_z0_p; float* zout = g_z1_p;
    for (int it = 0; it < 6; it++) {
        // az = a @ z
        sgemm<false,false,false><<<dim3(4, 2, 64), 256>>>(
            g_attn2_p, zin, g_az_p, 256, 256, 256, 256,
            65536LL, 65536LL, 65536LL, 0.f, 1.f, nullptr);
        // t2 = az @ (7I - az)
        sgemm<false,true,false><<<dim3(4, 2, 64), 256>>>(
            g_az_p, g_az_p, g_t2_p, 256, 256, 256, 256,
            65536LL, 65536LL, 65536LL, 7.f, 1.f, nullptr);
        // t4 = az @ (15I - t2)
        sgemm<false,true,false><<<dim3(4, 2, 64), 256>>>(
            g_az_p, g_t2_p, g_t4_p, 256, 256, 256, 256,
            65536LL, 65536LL, 65536LL, 15.f, 1.f, nullptr);
        // z' = 0.25 * z @ (13I - t4)
        sgemm<false,true,false><<<dim3(4, 2, 64), 256>>>(
            zin, g_t4_p, zout, 256, 256, 256, 256,
            65536LL, 65536LL, 65536LL, 13.f, 0.25f, nullptr);
        float* tmp = zin; zin = zout; zout = tmp;
    }
    // zin == final pseudo-inverse

    // 10. a3v = attn3 @ V   [256,4096]@[4096,64]
    sgemm<false,false,false><<<dim3(1, 2, 64), 256>>>(
        g_attn3_p, g_V_p, g_a3v_p, 4096, 4096, 64, 64,
        1048576LL, 262144LL, 16384LL, 0.f, 1.f, nullptr);

    // 11. tmp2 = z @ a3v   [256,256]@[256,64]
    sgemm<false,false,false><<<dim3(1, 2, 64), 256>>>(
        zin, g_a3v_p, g_tmp2_p, 256, 256, 64, 64,
        65536LL, 16384LL, 16384LL, 0.f, 1.f, nullptr);

    // 12. out = attn1 @ tmp2   [4096,256]@[256,64]
    sgemm<false,false,false><<<dim3(1, 32, 64), 256>>>(
        g_attn1_p, g_tmp2_p, g_out_p, 256, 256, 64, 64,
        1048576LL, 16384LL, 262144LL, 0.f, 1.f, nullptr);

    // 13. depthwise conv residual
    conv_kernel<<<65536, 256>>>(g_out_p, w_conv, g_out2_p);

    // 14. [b,h,n,d] -> [b,n,inner]
    to_bnd_kernel<<<65536, 256>>>(g_out2_p, g_outT_p);

    // 15. final fc: d_out = outT @ w_fc + b_fc   [16384,1024]@[1024,1024]
    sgemm<false,false,true><<<dim3(16, 128, 1), 256>>>(
        g_outT_p, w_fc, dout, 1024, 1024, 1024, 1024,
        0, 0, 0, 0.f, 1.f, b_fc);
}

// round 5
// speedup vs baseline: 2.1590x; 2.1590x over previous
#include <cuda_runtime.h>
#include <cstdint>

// ============================================================================
// NystromAttention — tf32 tensor-core version
//   b=4, n=4096, dim=1024, H=16, DH=64, M=256 landmarks, 6 MP iters, K=13 conv
// All matmuls use mma.sync.m16n8k8 tf32 (fp32 accum). CTA tile 128x64x32,
// 8 warps (4x2), warp tile 32x32. Batched over b*h via gridDim.z.
// ============================================================================

// ---------------- scratch (device globals; no allocation allowed) ----------
__device__ float g_qkv  [50331648];  // [16384, 3072]
__device__ float g_Q    [16777216];  // [b,h,n,d] scaled
__device__ float g_K    [16777216];
__device__ float g_V    [16777216];
__device__ float g_ql   [1048576];   // [bh, 256, 64]
__device__ float g_kl   [1048576];
__device__ float g_attn1[67108864];  // [bh, 4096, 256]
__device__ float g_attn3[67108864];  // [bh, 256, 4096]
__device__ float g_attn2[4194304];   // [bh, 256, 256]
__device__ float g_z0   [4194304];
__device__ float g_z1   [4194304];
__device__ float g_az   [4194304];
__device__ float g_t2   [4194304];
__device__ float g_t4   [4194304];
__device__ float g_a3v  [1048576];   // [bh, 256, 64]
__device__ float g_tmp2 [1048576];   // [bh, 256, 64]
__device__ float g_out  [16777216];  // [b,h,n,d]
__device__ float g_outT [16777216];  // [b,n,1024]
__device__ unsigned int g_m1, g_m2;  // global maxes for MP init

__device__ __forceinline__ unsigned f2tf(float f) {
    unsigned u;
    asm("cvt.rna.tf32.f32 %0, %1;" : "=r"(u) : "f"(f));
    return u;
}

// ---------------- tf32 tensor-core GEMM ------------------------------------
// C = outScale * A @ Beff (+ bias); Beff = B (NN), B^T (NT), or alpha*I - B.
// BM=128, BN=64, BK=32; 256 threads (8 warps, 4x2); warp tile 32x32.
// All problem dims are exact multiples of tiles — no bounds checks.
template<bool TRANSB, bool AIM, bool BIAS>
__global__ __launch_bounds__(256)
void tgemm(const float* __restrict__ A, const float* __restrict__ B,
           float* __restrict__ C, int Kdim, int lda, int ldb, int ldc,
           long long sA, long long sB, long long sC,
           float alpha, float outScale, const float* __restrict__ bias)
{
    constexpr int BM = 128, BN = 64, BK = 32;
    __shared__ unsigned As[BM][BK + 4];   // stride 36: frag LDS conflict-free
    __shared__ unsigned Bs[2304];         // NN: [32][72] k-major; NT: [64][36] n-major

    const float* Ab = A + (long long)blockIdx.z * sA;
    const float* Bb = B + (long long)blockIdx.z * sB;
    float*       Cb = C + (long long)blockIdx.z * sC;

    const int row0 = blockIdx.y * BM;
    const int col0 = blockIdx.x * BN;
    const int t    = threadIdx.x;
    const int lane = t & 31;
    const int w    = t >> 5;
    const int wm   = w & 3;         // warp row (0..3) -> rows wm*32
    const int wn   = w >> 2;        // warp col (0..1) -> cols wn*32
    const int g    = lane >> 2;     // group id (row within fragment)
    const int tg   = lane & 3;      // thread in group (k within fragment)

    float acc[2][4][4];
    #pragma unroll
    for (int mi = 0; mi < 2; mi++)
        #pragma unroll
        for (int ni = 0; ni < 4; ni++)
            #pragma unroll
            for (int q = 0; q < 4; q++) acc[mi][ni][q] = 0.f;

    for (int k0 = 0; k0 < Kdim; k0 += BK) {
        // ---- A tile: 128x32, row-major [m][k]
        #pragma unroll
        for (int l = 0; l < 4; l++) {
            int idx = t + l * 256;            // 0..1023
            int r   = idx >> 3;               // m 0..127
            int kq  = (idx & 7) << 2;         // k 0,4,..,28
            float4 av = *reinterpret_cast<const float4*>(
                Ab + (long long)(row0 + r) * lda + k0 + kq);
            uint4 u = make_uint4(f2tf(av.x), f2tf(av.y), f2tf(av.z), f2tf(av.w));
            *reinterpret_cast<uint4*>(&As[r][kq]) = u;
        }
        // ---- B tile
        if (!TRANSB) {
            // global [k][n] -> Bs[k*72 + n]
            #pragma unroll
            for (int l = 0; l < 2; l++) {
                int idx = t + l * 256;        // 0..511
                int r   = idx >> 4;           // k 0..31
                int cq  = (idx & 15) << 2;    // n 0,4,..,60
                float4 bv = *reinterpret_cast<const float4*>(
                    Bb + (long long)(k0 + r) * ldb + col0 + cq);
                if (AIM) {
                    int gk = k0 + r, gj = col0 + cq;
                    bv.x = ((gk == gj    ) ? alpha : 0.f) - bv.x;
                    bv.y = ((gk == gj + 1) ? alpha : 0.f) - bv.y;
                    bv.z = ((gk == gj + 2) ? alpha : 0.f) - bv.z;
                    bv.w = ((gk == gj + 3) ? alpha : 0.f) - bv.w;
                }
                uint4 u = make_uint4(f2tf(bv.x), f2tf(bv.y), f2tf(bv.z), f2tf(bv.w));
                *reinterpret_cast<uint4*>(&Bs[r * 72 + cq]) = u;
            }
        } else {
            // global [n][k] -> Bs[n*36 + k]
            #pragma unroll
            for (int l = 0; l < 2; l++) {
                int idx = t + l * 256;        // 0..511
                int j   = idx >> 3;           // n 0..63
                int kq  = (idx & 7) << 2;     // k 0,4,..,28
                float4 bv = *reinterpret_cast<const float4*>(
                    Bb + (long long)(col0 + j) * ldb + k0 + kq);
                uint4 u = make_uint4(f2tf(bv.x), f2tf(bv.y), f2tf(bv.z), f2tf(bv.w));
                *reinterpret_cast<uint4*>(&Bs[j * 36 + kq]) = u;
            }
        }
        __syncthreads();

        #pragma unroll
        for (int ks = 0; ks < 4; ks++) {
            const int kk = ks * 8;
            unsigned af[2][4], bf[4][2];
            #pragma unroll
            for (int mi = 0; mi < 2; mi++) {
                int rb = wm * 32 + mi * 16;
                af[mi][0] = As[rb + g     ][kk + tg];
                af[mi][1] = As[rb + 8 + g ][kk + tg];
                af[mi][2] = As[rb + g     ][kk + 4 + tg];
                af[mi][3] = As[rb + 8 + g ][kk + 4 + tg];
            }
            #pragma unroll
            for (int ni = 0; ni < 4; ni++) {
                int cb = wn * 32 + ni * 8;
                if (TRANSB) {
                    bf[ni][0] = Bs[(cb + g) * 36 + kk + tg];
                    bf[ni][1] = Bs[(cb + g) * 36 + kk + 4 + tg];
                } else {
                    bf[ni][0] = Bs[(kk + tg) * 72 + cb + g];
                    bf[ni][1] = Bs[(kk + 4 + tg) * 72 + cb + g];
                }
            }
            #pragma unroll
            for (int mi = 0; mi < 2; mi++)
                #pragma unroll
                for (int ni = 0; ni < 4; ni++)
                    asm volatile(
                        "mma.sync.aligned.m16n8k8.row.col.f32.tf32.tf32.f32 "
                        "{%0,%1,%2,%3}, {%4,%5,%6,%7}, {%8,%9}, {%0,%1,%2,%3};"
                        : "+f"(acc[mi][ni][0]), "+f"(acc[mi][ni][1]),
                          "+f"(acc[mi][ni][2]), "+f"(acc[mi][ni][3])
                        : "r"(af[mi][0]), "r"(af[mi][1]),
                          "r"(af[mi][2]), "r"(af[mi][3]),
                          "r"(bf[ni][0]), "r"(bf[ni][1]));
        }
        __syncthreads();
    }

    // ---- epilogue
    #pragma unroll
    for (int mi = 0; mi < 2; mi++) {
        int r = row0 + wm * 32 + mi * 16 + g;
        #pragma unroll
        for (int ni = 0; ni < 4; ni++) {
            int c = col0 + wn * 32 + ni * 8 + 2 * tg;
            float b0 = 0.f, b1 = 0.f;
            if (BIAS) { b0 = bias[c]; b1 = bias[c + 1]; }
            float2 o0 = make_float2(acc[mi][ni][0] * outScale + b0,
                                    acc[mi][ni][1] * outScale + b1);
            float2 o1 = make_float2(acc[mi][ni][2] * outScale + b0,
                                    acc[mi][ni][3] * outScale + b1);
            *reinterpret_cast<float2*>(Cb + (long long)r * ldc + c)       = o0;
            *reinterpret_cast<float2*>(Cb + (long long)(r + 8) * ldc + c) = o1;
        }
    }
}

// ---------------- elementwise / reductions ---------------------------------
__global__ void split_qkv_kernel(const float* __restrict__ qkv,
                                 float* __restrict__ Q, float* __restrict__ K,
                                 float* __restrict__ V)
{
    long long i = (long long)blockIdx.x * 256 + threadIdx.x;   // < 16777216
    int d = (int)(i & 63);
    int n = (int)((i >> 6) & 4095);
    int h = (int)((i >> 18) & 15);
    int b = (int)(i >> 22);
    long long src = ((long long)(b * 4096 + n)) * 3072 + h * 64 + d;
    Q[i] = qkv[src] * 0.125f;
    K[i] = qkv[src + 1024];
    V[i] = qkv[src + 2048];
}

__global__ void landmarks_kernel(const float* __restrict__ Q,
                                 const float* __restrict__ K,
                                 float* __restrict__ ql, float* __restrict__ kl)
{
    int i = blockIdx.x * 256 + threadIdx.x;       // < 1048576  [bh,m,d]
    int d = i & 63;
    int m = (i >> 6) & 255;
    int bh = i >> 14;
    long long base = ((long long)bh * 4096 + m * 16) * 64 + d;
    float sq = 0.f, sk = 0.f;
    #pragma unroll
    for (int j = 0; j < 16; j++) {
        sq += Q[base + j * 64];
        sk += K[base + j * 64];
    }
    ql[i] = sq * 0.0625f;
    kl[i] = sk * 0.0625f;
}

__global__ void softmax256_kernel(float* __restrict__ data, int rows)
{
    int gw   = (int)((blockIdx.x * (long long)blockDim.x + threadIdx.x) >> 5);
    int lane = threadIdx.x & 31;
    if (gw >= rows) return;
    float* p = data + (long long)gw * 256;
    float v[8];
    float mx = -1e30f;
    #pragma unroll
    for (int i = 0; i < 8; i++) { v[i] = p[lane + 32 * i]; mx = fmaxf(mx, v[i]); }
    #pragma unroll
    for (int o = 16; o > 0; o >>= 1) mx = fmaxf(mx, __shfl_xor_sync(0xffffffffu, mx, o));
    float s = 0.f;
    #pragma unroll
    for (int i = 0; i < 8; i++) { v[i] = expf(v[i] - mx); s += v[i]; }
    #pragma unroll
    for (int o = 16; o > 0; o >>= 1) s += __shfl_xor_sync(0xffffffffu, s, o);
    float inv = 1.f / s;
    #pragma unroll
    for (int i = 0; i < 8; i++) p[lane + 32 * i] = v[i] * inv;
}

__global__ void softmax4096_kernel(float* __restrict__ data)
{
    float* p = data + (long long)blockIdx.x * 4096;
    int t = threadIdx.x;
    float v[16];
    float mx = -1e30f;
    #pragma unroll
    for (int i = 0; i < 16; i++) { v[i] = p[t + 256 * i]; mx = fmaxf(mx, v[i]); }
    __shared__ float red[256];
    red[t] = mx; __syncthreads();
    for (int s = 128; s > 0; s >>= 1) {
        if (t < s) red[t] = fmaxf(red[t], red[t + s]);
        __syncthreads();
    }
    mx = red[0]; __syncthreads();
    float sum = 0.f;
    #pragma unroll
    for (int i = 0; i < 16; i++) { v[i] = expf(v[i] - mx); sum += v[i]; }
    red[t] = sum; __syncthreads();
    for (int s = 128; s > 0; s >>= 1) {
        if (t < s) red[t] += red[t + s];
        __syncthreads();
    }
    float inv = 1.f / red[0];
    #pragma unroll
    for (int i = 0; i < 16; i++) p[t + 256 * i] = v[i] * inv;
}

__global__ void mp_reset_kernel() { g_m1 = 0u; g_m2 = 0u; }

__global__ void mp_reduce_kernel(const float* __restrict__ a)
{
    int bh = blockIdx.x;
    int j  = threadIdx.x;
    const float* p = a + (long long)bh * 65536;
    float rs = 0.f, cs = 0.f;
    for (int i = 0; i < 256; i++) {
        rs += fabsf(p[j * 256 + i]);
        cs += fabsf(p[i * 256 + j]);
    }
    __shared__ float r1[256], r2[256];
    r1[j] = rs; r2[j] = cs; __syncthreads();
    for (int s = 128; s > 0; s >>= 1) {
        if (j < s) { r1[j] = fmaxf(r1[j], r1[j + s]); r2[j] = fmaxf(r2[j], r2[j + s]); }
        __syncthreads();
    }
    if (j == 0) {
        atomicMax(&g_m1, __float_as_uint(r1[0]));
        atomicMax(&g_m2, __float_as_uint(r2[0]));
    }
}

__global__ void mp_init_kernel(const float* __restrict__ a, float* __restrict__ z)
{
    long long i = (long long)blockIdx.x * 256 + threadIdx.x;  // < 4194304
    int col = (int)(i & 255);
    int row = (int)((i >> 8) & 255);
    long long bh = i >> 16;
    float denom = __uint_as_float(g_m1) * __uint_as_float(g_m2);
    z[i] = a[bh * 65536 + (long long)col * 256 + row] / denom;
}

// fused: depthwise residual conv (K=13, pad 6) + [b,h,n,d] -> [b,n,h*64+d]
__global__ void conv_tr_kernel(const float* __restrict__ src,
                               const float* __restrict__ w,   // [16,13]
                               float* __restrict__ dst)
{
    long long o = (long long)blockIdx.x * 256 + threadIdx.x;  // < 16777216 (b,n,h,d)
    int d = (int)(o & 63);
    int h = (int)((o >> 6) & 15);
    int n = (int)((o >> 10) & 4095);
    int b = (int)(o >> 22);
    long long s = (((long long)(b * 16 + h)) * 4096 + n) * 64 + d;
    float v = src[s];
    float r = 0.f;
    #pragma unroll
    for (int tt = 0; tt < 13; tt++) {
        int nn = n + tt - 6;
        if (nn >= 0 && nn < 4096)
            r += w[h * 13 + tt] * src[s + (long long)(tt - 6) * 64];
    }
    dst[o] = v + r;
}

// ---------------- launch ----------------------------------------------------
extern "C" void kernel_launch(void* const* d_in, const int* in_sizes, int n_in,
                              void* d_out, int out_size)
{
    (void)in_sizes; (void)n_in; (void)out_size;
    const float* x      = (const float*)d_in[0];
    const float* w_qkv  = (const float*)d_in[1];
    const float* w_conv = (const float*)d_in[2];
    const float* w_fc   = (const float*)d_in[3];
    const float* b_fc   = (const float*)d_in[4];
    float* dout = (float*)d_out;

    void* vp;
    #define SYMP(nm) float* nm##_p; cudaGetSymbolAddress(&vp, nm); nm##_p = (float*)vp;
    SYMP(g_qkv)  SYMP(g_Q)    SYMP(g_K)    SYMP(g_V)
    SYMP(g_ql)   SYMP(g_kl)
    SYMP(g_attn1) SYMP(g_attn3) SYMP(g_attn2)
    SYMP(g_z0)   SYMP(g_z1)   SYMP(g_az)   SYMP(g_t2) SYMP(g_t4)
    SYMP(g_a3v)  SYMP(g_tmp2)
    SYMP(g_out)  SYMP(g_outT)
    #undef SYMP

    // 1. qkv = x @ w_qkv   [16384,1024]@[1024,3072]
    tgemm<false,false,false><<<dim3(48, 128, 1), 256>>>(
        x, w_qkv, g_qkv_p, 1024, 1024, 3072, 3072, 0, 0, 0, 0.f, 1.f, nullptr);

    // 2. split + scale
    split_qkv_kernel<<<65536, 256>>>(g_qkv_p, g_Q_p, g_K_p, g_V_p);

    // 3. landmarks
    landmarks_kernel<<<4096, 256>>>(g_Q_p, g_K_p, g_ql_p, g_kl_p);

    // 4. sim1 = Q @ kl^T   [4096,64]@[256,64]^T  (batch 64)
    tgemm<true,false,false><<<dim3(4, 32, 64), 256>>>(
        g_Q_p, g_kl_p, g_attn1_p, 64, 64, 64, 256,
        262144LL, 16384LL, 1048576LL, 0.f, 1.f, nullptr);

    // 5. sim2 = ql @ kl^T  [256,64]@[256,64]^T
    tgemm<true,false,false><<<dim3(4, 2, 64), 256>>>(
        g_ql_p, g_kl_p, g_attn2_p, 64, 64, 64, 256,
        16384LL, 16384LL, 65536LL, 0.f, 1.f, nullptr);

    // 6. sim3 = ql @ K^T   [256,64]@[4096,64]^T
    tgemm<true,false,false><<<dim3(64, 2, 64), 256>>>(
        g_ql_p, g_K_p, g_attn3_p, 64, 64, 64, 4096,
        16384LL, 262144LL, 1048576LL, 0.f, 1.f, nullptr);

    // 7. softmaxes (in place)
    softmax256_kernel<<<32768, 256>>>(g_attn1_p, 262144);
    softmax256_kernel<<<2048, 256>>>(g_attn2_p, 16384);
    softmax4096_kernel<<<16384, 256>>>(g_attn3_p);

    // 8. MP init: z0 = attn2^T / (max(rowsum)*max(colsum))
    mp_reset_kernel<<<1, 1>>>();
    mp_reduce_kernel<<<64, 256>>>(g_attn2_p);
    mp_init_kernel<<<16384, 256>>>(g_attn2_p, g_z0_p);

    // 9. 6 Newton-Schulz iterations (batched 256^3 GEMMs)
    float* zin = g_z0_p; float* zout = g_z1_p;
    for (int it = 0; it < 6; it++) {
        tgemm<false,false,false><<<dim3(4, 2, 64), 256>>>(
            g_attn2_p, zin, g_az_p, 256, 256, 256, 256,
            65536LL, 65536LL, 65536LL, 0.f, 1.f, nullptr);
        tgemm<false,true,false><<<dim3(4, 2, 64), 256>>>(
            g_az_p, g_az_p, g_t2_p, 256, 256, 256, 256,
            65536LL, 65536LL, 65536LL, 7.f, 1.f, nullptr);
        tgemm<false,true,false><<<dim3(4, 2, 64), 256>>>(
            g_az_p, g_t2_p, g_t4_p, 256, 256, 256, 256,
            65536LL, 65536LL, 65536LL, 15.f, 1.f, nullptr);
        tgemm<false,true,false><<<dim3(4, 2, 64), 256>>>(
            zin, g_t4_p, zout, 256, 256, 256, 256,
            65536LL, 65536LL, 65536LL, 13.f, 0.25f, nullptr);
        float* tmp = zin; zin = zout; zout = tmp;
    }

    // 10. a3v = attn3 @ V   [256,4096]@[4096,64]
    tgemm<false,false,false><<<dim3(1, 2, 64), 256>>>(
        g_attn3_p, g_V_p, g_a3v_p, 4096, 4096, 64, 64,
        1048576LL, 262144LL, 16384LL, 0.f, 1.f, nullptr);

    // 11. tmp2 = z @ a3v   [256,256]@[256,64]
    tgemm<false,false,false><<<dim3(1, 2, 64), 256>>>(
        zin, g_a3v_p, g_tmp2_p, 256, 256, 64, 64,
        65536LL, 16384LL, 16384LL, 0.f, 1.f, nullptr);

    // 12. out = attn1 @ tmp2   [4096,256]@[256,64]
    tgemm<false,false,false><<<dim3(1, 32, 64), 256>>>(
        g_attn1_p, g_tmp2_p, g_out_p, 256, 256, 64, 64,
        1048576LL, 16384LL, 262144LL, 0.f, 1.f, nullptr);

    // 13. fused depthwise conv residual + transpose to [b,n,inner]
    conv_tr_kernel<<<65536, 256>>>(g_out_p, w_conv, g_outT_p);

    // 14. final fc: d_out = outT @ w_fc + b_fc   [16384,1024]@[1024,1024]
    tgemm<false,false,true><<<dim3(16, 128, 1), 256>>>(
        g_outT_p, w_fc, dout, 1024, 1024, 1024, 1024,
        0, 0, 0, 0.f, 1.f, b_fc);
}

// round 6
// speedup vs baseline: 2.4730x; 1.1455x over previous
#include <cuda_runtime.h>
#include <cstdint>

// ============================================================================
// NystromAttention — tf32 tensor cores, double-buffered smem pipeline
//   b=4, n=4096, dim=1024, H=16, DH=64, M=256 landmarks, 6 MP iters, K=13 conv
// mma.sync.m16n8k8 tf32 (fp32 accum). CTA tile 128x64x32, 8 warps (4x2),
// warp tile 32x32, 2-stage smem double buffering. Batched over b*h via grid.z.
// ============================================================================

// ---------------- scratch (device globals; no allocation allowed) ----------
__device__ float g_Q    [16777216];  // [b,h,n,d] scaled
__device__ float g_K    [16777216];
__device__ float g_V    [16777216];
__device__ float g_ql   [1048576];   // [bh, 256, 64]
__device__ float g_kl   [1048576];
__device__ float g_attn1[67108864];  // [bh, 4096, 256]
__device__ float g_attn3[67108864];  // [bh, 256, 4096]
__device__ float g_attn2[4194304];   // [bh, 256, 256]
__device__ float g_z0   [4194304];
__device__ float g_z1   [4194304];
__device__ float g_az   [4194304];
__device__ float g_t2   [4194304];
__device__ float g_t4   [4194304];
__device__ float g_a3v  [1048576];   // [bh, 256, 64]
__device__ float g_tmp2 [1048576];   // [bh, 256, 64]
__device__ float g_out  [16777216];  // [b,h,n,d]
__device__ float g_outT [16777216];  // [b,n,1024]
__device__ unsigned int g_m1, g_m2;  // global maxes for MP init

__device__ __forceinline__ unsigned f2tf(float f) {
    unsigned u;
    asm("cvt.rna.tf32.f32 %0, %1;" : "=r"(u) : "f"(f));
    return u;
}

// ---------------- tf32 tensor-core GEMM ------------------------------------
// C = outScale * A @ Beff (+ bias); Beff = B (NN), B^T (NT), or alpha*I - B.
// QKVE: epilogue scatters to Q/K/V in [b,h,n,d] (QKV projection fusion).
// SPLITK: grid.z = bh*8+ks; accumulate into C with atomicAdd (C pre-zeroed).
// BM=128, BN=64, BK=32; 256 threads; 2-stage double buffer (54KB dyn smem).
template<bool TRANSB, bool AIM, bool BIAS, bool QKVE, bool SPLITK>
__global__ __launch_bounds__(256)
void tgemm(const float* __restrict__ A, const float* __restrict__ B,
           float* __restrict__ C, int Kdim, int lda, int ldb, int ldc,
           long long sA, long long sB, long long sC,
           float alpha, float outScale, const float* __restrict__ bias,
           float* __restrict__ qp, float* __restrict__ kp,
           float* __restrict__ vp)
{
    extern __shared__ unsigned sh[];
    unsigned* As = sh;                 // [2][128][36]
    unsigned* Bs = sh + 2 * 128 * 36;  // [2][2304]  NN:[32][72] / NT:[64][36]

    const float* Ab;
    const float* Bb;
    float*       Cb;
    if (SPLITK) {
        int bh = blockIdx.z >> 3, ks = blockIdx.z & 7;
        Ab = A + (long long)bh * sA + (long long)ks * Kdim;
        Bb = B + (long long)bh * sB + (long long)ks * Kdim * ldb;
        Cb = C + (long long)bh * sC;
    } else {
        Ab = A + (long long)blockIdx.z * sA;
        Bb = B + (long long)blockIdx.z * sB;
        Cb = C + (long long)blockIdx.z * sC;
    }

    const int row0 = blockIdx.y * 128;
    const int col0 = blockIdx.x * 64;
    const int t    = threadIdx.x;
    const int lane = t & 31;
    const int w    = t >> 5;
    const int wm   = w & 3;
    const int wn   = w >> 2;
    const int g    = lane >> 2;
    const int tg   = lane & 3;

    // staging registers
    float4 aR[4];
    float4 bR[2];

    auto ldA = [&](int k0) {
        #pragma unroll
        for (int l = 0; l < 4; l++) {
            int idx = t + l * 256;
            int r   = idx >> 3;
            int kq  = (idx & 7) << 2;
            aR[l] = *reinterpret_cast<const float4*>(
                Ab + (long long)(row0 + r) * lda + k0 + kq);
        }
    };
    auto stA = [&](int st) {
        unsigned* Ap = As + st * 4608;
        #pragma unroll
        for (int l = 0; l < 4; l++) {
            int idx = t + l * 256;
            int r   = idx >> 3;
            int kq  = (idx & 7) << 2;
            uint4 u = make_uint4(f2tf(aR[l].x), f2tf(aR[l].y),
                                 f2tf(aR[l].z), f2tf(aR[l].w));
            *reinterpret_cast<uint4*>(Ap + r * 36 + kq) = u;
        }
    };
    auto ldB = [&](int k0) {
        #pragma unroll
        for (int l = 0; l < 2; l++) {
            int idx = t + l * 256;
            if (!TRANSB) {
                int r  = idx >> 4;
                int cq = (idx & 15) << 2;
                bR[l] = *reinterpret_cast<const float4*>(
                    Bb + (long long)(k0 + r) * ldb + col0 + cq);
            } else {
                int j  = idx >> 3;
                int kq = (idx & 7) << 2;
                bR[l] = *reinterpret_cast<const float4*>(
                    Bb + (long long)(col0 + j) * ldb + k0 + kq);
            }
        }
    };
    auto stB = [&](int st, int k0) {
        unsigned* Bp = Bs + st * 2304;
        #pragma unroll
        for (int l = 0; l < 2; l++) {
            int idx = t + l * 256;
            float4 bv = bR[l];
            if (!TRANSB) {
                int r  = idx >> 4;
                int cq = (idx & 15) << 2;
                if (AIM) {
                    int gk = k0 + r, gj = col0 + cq;
                    bv.x = ((gk == gj    ) ? alpha : 0.f) - bv.x;
                    bv.y = ((gk == gj + 1) ? alpha : 0.f) - bv.y;
                    bv.z = ((gk == gj + 2) ? alpha : 0.f) - bv.z;
                    bv.w = ((gk == gj + 3) ? alpha : 0.f) - bv.w;
                }
                uint4 u = make_uint4(f2tf(bv.x), f2tf(bv.y),
                                     f2tf(bv.z), f2tf(bv.w));
                *reinterpret_cast<uint4*>(Bp + r * 72 + cq) = u;
            } else {
                int j  = idx >> 3;
                int kq = (idx & 7) << 2;
                uint4 u = make_uint4(f2tf(bv.x), f2tf(bv.y),
                                     f2tf(bv.z), f2tf(bv.w));
                *reinterpret_cast<uint4*>(Bp + j * 36 + kq) = u;
            }
        }
    };

    float acc[2][4][4];
    #pragma unroll
    for (int mi = 0; mi < 2; mi++)
        #pragma unroll
        for (int ni = 0; ni < 4; ni++)
            #pragma unroll
            for (int q = 0; q < 4; q++) acc[mi][ni][q] = 0.f;

    // prologue
    ldA(0); ldB(0);
    stA(0); stB(0, 0);
    __syncthreads();

    int s = 0;
    for (int k0 = 0; k0 < Kdim; k0 += 32) {
        bool more = (k0 + 32 < Kdim);
        if (more) { ldA(k0 + 32); ldB(k0 + 32); }

        const unsigned* Ap = As + s * 4608;
        const unsigned* Bp = Bs + s * 2304;
        #pragma unroll
        for (int ks = 0; ks < 4; ks++) {
            const int kk = ks * 8;
            unsigned af[2][4], bf[4][2];
            #pragma unroll
            for (int mi = 0; mi < 2; mi++) {
                int rb = wm * 32 + mi * 16;
                af[mi][0] = Ap[(rb + g    ) * 36 + kk + tg];
                af[mi][1] = Ap[(rb + 8 + g) * 36 + kk + tg];
                af[mi][2] = Ap[(rb + g    ) * 36 + kk + 4 + tg];
                af[mi][3] = Ap[(rb + 8 + g) * 36 + kk + 4 + tg];
            }
            #pragma unroll
            for (int ni = 0; ni < 4; ni++) {
                int cb = wn * 32 + ni * 8;
                if (TRANSB) {
                    bf[ni][0] = Bp[(cb + g) * 36 + kk + tg];
                    bf[ni][1] = Bp[(cb + g) * 36 + kk + 4 + tg];
                } else {
                    bf[ni][0] = Bp[(kk + tg) * 72 + cb + g];
                    bf[ni][1] = Bp[(kk + 4 + tg) * 72 + cb + g];
                }
            }
            #pragma unroll
            for (int mi = 0; mi < 2; mi++)
                #pragma unroll
                for (int ni = 0; ni < 4; ni++)
                    asm volatile(
                        "mma.sync.aligned.m16n8k8.row.col.f32.tf32.tf32.f32 "
                        "{%0,%1,%2,%3}, {%4,%5,%6,%7}, {%8,%9}, {%0,%1,%2,%3};"
                        : "+f"(acc[mi][ni][0]), "+f"(acc[mi][ni][1]),
                          "+f"(acc[mi][ni][2]), "+f"(acc[mi][ni][3])
                        : "r"(af[mi][0]), "r"(af[mi][1]),
                          "r"(af[mi][2]), "r"(af[mi][3]),
                          "r"(bf[ni][0]), "r"(bf[ni][1]));
        }

        if (more) {
            stA(s ^ 1); stB(s ^ 1, k0 + 32);
            __syncthreads();
        }
        s ^= 1;
    }

    // ---- epilogue
    #pragma unroll
    for (int mi = 0; mi < 2; mi++) {
        int r = row0 + wm * 32 + mi * 16 + g;
        #pragma unroll
        for (int ni = 0; ni < 4; ni++) {
            int c = col0 + wn * 32 + ni * 8 + 2 * tg;
            if (QKVE) {
                int which = c >> 10, hh = (c >> 6) & 15, d = c & 63;
                float sc = (which == 0) ? 0.125f : 1.f;
                float* dst = (which == 0) ? qp : ((which == 1) ? kp : vp);
                long long base =
                    (((long long)((r >> 12) * 16 + hh)) * 4096 + (r & 4095)) * 64 + d;
                *reinterpret_cast<float2*>(dst + base) =
                    make_float2(acc[mi][ni][0] * sc, acc[mi][ni][1] * sc);
                *reinterpret_cast<float2*>(dst + base + 512) =
                    make_float2(acc[mi][ni][2] * sc, acc[mi][ni][3] * sc);
            } else if (SPLITK) {
                float* p0 = Cb + (long long)r * ldc + c;
                atomicAdd(p0,                          acc[mi][ni][0]);
                atomicAdd(p0 + 1,                      acc[mi][ni][1]);
                atomicAdd(p0 + (long long)8 * ldc,     acc[mi][ni][2]);
                atomicAdd(p0 + (long long)8 * ldc + 1, acc[mi][ni][3]);
            } else {
                float b0 = 0.f, b1 = 0.f;
                if (BIAS) { b0 = bias[c]; b1 = bias[c + 1]; }
                float2 o0 = make_float2(acc[mi][ni][0] * outScale + b0,
                                        acc[mi][ni][1] * outScale + b1);
                float2 o1 = make_float2(acc[mi][ni][2] * outScale + b0,
                                        acc[mi][ni][3] * outScale + b1);
                *reinterpret_cast<float2*>(Cb + (long long)r * ldc + c)       = o0;
                *reinterpret_cast<float2*>(Cb + (long long)(r + 8) * ldc + c) = o1;
            }
        }
    }
}

// ---------------- elementwise / reductions ---------------------------------
__global__ void landmarks_kernel(const float* __restrict__ Q,
                                 const float* __restrict__ K,
                                 float* __restrict__ ql, float* __restrict__ kl)
{
    int i = blockIdx.x * 256 + threadIdx.x;       // < 1048576  [bh,m,d]
    int d = i & 63;
    int m = (i >> 6) & 255;
    int bh = i >> 14;
    long long base = ((long long)bh * 4096 + m * 16) * 64 + d;
    float sq = 0.f, sk = 0.f;
    #pragma unroll
    for (int j = 0; j < 16; j++) {
        sq += Q[base + j * 64];
        sk += K[base + j * 64];
    }
    ql[i] = sq * 0.0625f;
    kl[i] = sk * 0.0625f;
}

__global__ void softmax256_kernel(float* __restrict__ data, int rows)
{
    int gw   = (int)((blockIdx.x * (long long)blockDim.x + threadIdx.x) >> 5);
    int lane = threadIdx.x & 31;
    if (gw >= rows) return;
    float* p = data + (long long)gw * 256;
    float v[8];
    float mx = -1e30f;
    #pragma unroll
    for (int i = 0; i < 8; i++) { v[i] = p[lane + 32 * i]; mx = fmaxf(mx, v[i]); }
    #pragma unroll
    for (int o = 16; o > 0; o >>= 1) mx = fmaxf(mx, __shfl_xor_sync(0xffffffffu, mx, o));
    float s = 0.f;
    #pragma unroll
    for (int i = 0; i < 8; i++) { v[i] = expf(v[i] - mx); s += v[i]; }
    #pragma unroll
    for (int o = 16; o > 0; o >>= 1) s += __shfl_xor_sync(0xffffffffu, s, o);
    float inv = 1.f / s;
    #pragma unroll
    for (int i = 0; i < 8; i++) p[lane + 32 * i] = v[i] * inv;
}

__global__ void softmax4096_kernel(float* __restrict__ data)
{
    float* p = data + (long long)blockIdx.x * 4096;
    int t = threadIdx.x;
    float v[16];
    float mx = -1e30f;
    #pragma unroll
    for (int i = 0; i < 16; i++) { v[i] = p[t + 256 * i]; mx = fmaxf(mx, v[i]); }
    __shared__ float red[256];
    red[t] = mx; __syncthreads();
    for (int s = 128; s > 0; s >>= 1) {
        if (t < s) red[t] = fmaxf(red[t], red[t + s]);
        __syncthreads();
    }
    mx = red[0]; __syncthreads();
    float sum = 0.f;
    #pragma unroll
    for (int i = 0; i < 16; i++) { v[i] = expf(v[i] - mx); sum += v[i]; }
    red[t] = sum; __syncthreads();
    for (int s = 128; s > 0; s >>= 1) {
        if (t < s) red[t] += red[t + s];
        __syncthreads();
    }
    float inv = 1.f / red[0];
    #pragma unroll
    for (int i = 0; i < 16; i++) p[t + 256 * i] = v[i] * inv;
}

__global__ void mp_reset_kernel() { g_m1 = 0u; g_m2 = 0u; }

__global__ void mp_reduce_kernel(const float* __restrict__ a)
{
    int bh = blockIdx.x;
    int j  = threadIdx.x;
    const float* p = a + (long long)bh * 65536;
    float rs = 0.f, cs = 0.f;
    for (int i = 0; i < 256; i++) {
        rs += fabsf(p[j * 256 + i]);
        cs += fabsf(p[i * 256 + j]);
    }
    __shared__ float r1[256], r2[256];
    r1[j] = rs; r2[j] = cs; __syncthreads();
    for (int s = 128; s > 0; s >>= 1) {
        if (j < s) { r1[j] = fmaxf(r1[j], r1[j + s]); r2[j] = fmaxf(r2[j], r2[j + s]); }
        __syncthreads();
    }
    if (j == 0) {
        atomicMax(&g_m1, __float_as_uint(r1[0]));
        atomicMax(&g_m2, __float_as_uint(r2[0]));
    }
}

__global__ void mp_init_kernel(const float* __restrict__ a, float* __restrict__ z)
{
    long long i = (long long)blockIdx.x * 256 + threadIdx.x;  // < 4194304
    int col = (int)(i & 255);
    int row = (int)((i >> 8) & 255);
    long long bh = i >> 16;
    float denom = __uint_as_float(g_m1) * __uint_as_float(g_m2);
    z[i] = a[bh * 65536 + (long long)col * 256 + row] / denom;
}

// fused: depthwise residual conv (K=13, pad 6) + [b,h,n,d] -> [b,n,h*64+d]
__global__ void conv_tr_kernel(const float* __restrict__ src,
                               const float* __restrict__ w,   // [16,13]
                               float* __restrict__ dst)
{
    long long o = (long long)blockIdx.x * 256 + threadIdx.x;  // < 16777216 (b,n,h,d)
    int d = (int)(o & 63);
    int h = (int)((o >> 6) & 15);
    int n = (int)((o >> 10) & 4095);
    int b = (int)(o >> 22);
    long long s = (((long long)(b * 16 + h)) * 4096 + n) * 64 + d;
    float v = src[s];
    float r = 0.f;
    #pragma unroll
    for (int tt = 0; tt < 13; tt++) {
        int nn = n + tt - 6;
        if (nn >= 0 && nn < 4096)
            r += w[h * 13 + tt] * src[s + (long long)(tt - 6) * 64];
    }
    dst[o] = v + r;
}

// ---------------- launch ----------------------------------------------------
static constexpr int SMEM_BYTES = (2 * 128 * 36 + 2 * 2304) * 4;  // 55296

extern "C" void kernel_launch(void* const* d_in, const int* in_sizes, int n_in,
                              void* d_out, int out_size)
{
    (void)in_sizes; (void)n_in; (void)out_size;
    const float* x      = (const float*)d_in[0];
    const float* w_qkv  = (const float*)d_in[1];
    const float* w_conv = (const float*)d_in[2];
    const float* w_fc   = (const float*)d_in[3];
    const float* b_fc   = (const float*)d_in[4];
    float* dout = (float*)d_out;

    void* vp_;
    #define SYMP(nm) float* nm##_p; cudaGetSymbolAddress(&vp_, nm); nm##_p = (float*)vp_;
    SYMP(g_Q)    SYMP(g_K)    SYMP(g_V)
    SYMP(g_ql)   SYMP(g_kl)
    SYMP(g_attn1) SYMP(g_attn3) SYMP(g_attn2)
    SYMP(g_z0)   SYMP(g_z1)   SYMP(g_az)   SYMP(g_t2) SYMP(g_t4)
    SYMP(g_a3v)  SYMP(g_tmp2)
    SYMP(g_out)  SYMP(g_outT)
    #undef SYMP

    // allow 54KB dynamic smem on all instantiations
    cudaFuncSetAttribute(tgemm<false,false,false,true ,false>,
                         cudaFuncAttributeMaxDynamicSharedMemorySize, SMEM_BYTES);
    cudaFuncSetAttribute(tgemm<true ,false,false,false,false>,
                         cudaFuncAttributeMaxDynamicSharedMemorySize, SMEM_BYTES);
    cudaFuncSetAttribute(tgemm<false,false,false,false,false>,
                         cudaFuncAttributeMaxDynamicSharedMemorySize, SMEM_BYTES);
    cudaFuncSetAttribute(tgemm<false,true ,false,false,false>,
                         cudaFuncAttributeMaxDynamicSharedMemorySize, SMEM_BYTES);
    cudaFuncSetAttribute(tgemm<false,false,false,false,true >,
                         cudaFuncAttributeMaxDynamicSharedMemorySize, SMEM_BYTES);
    cudaFuncSetAttribute(tgemm<false,false,true ,false,false>,
                         cudaFuncAttributeMaxDynamicSharedMemorySize, SMEM_BYTES);

    // 1. qkv projection fused with split+scale: writes g_Q/g_K/g_V directly
    tgemm<false,false,false,true,false><<<dim3(48, 128, 1), 256, SMEM_BYTES>>>(
        x, w_qkv, nullptr, 1024, 1024, 3072, 0, 0, 0, 0, 0.f, 1.f, nullptr,
        g_Q_p, g_K_p, g_V_p);

    // 2. landmarks
    landmarks_kernel<<<4096, 256>>>(g_Q_p, g_K_p, g_ql_p, g_kl_p);

    // 3. sim1 = Q @ kl^T   [4096,64]@[256,64]^T  (batch 64)
    tgemm<true,false,false,false,false><<<dim3(4, 32, 64), 256, SMEM_BYTES>>>(
        g_Q_p, g_kl_p, g_attn1_p, 64, 64, 64, 256,
        262144LL, 16384LL, 1048576LL, 0.f, 1.f, nullptr, nullptr, nullptr, nullptr);

    // 4. sim2 = ql @ kl^T  [256,64]@[256,64]^T
    tgemm<true,false,false,false,false><<<dim3(4, 2, 64), 256, SMEM_BYTES>>>(
        g_ql_p, g_kl_p, g_attn2_p, 64, 64, 64, 256,
        16384LL, 16384LL, 65536LL, 0.f, 1.f, nullptr, nullptr, nullptr, nullptr);

    // 5. sim3 = ql @ K^T   [256,64]@[4096,64]^T
    tgemm<true,false,false,false,false><<<dim3(64, 2, 64), 256, SMEM_BYTES>>>(
        g_ql_p, g_K_p, g_attn3_p, 64, 64, 64, 4096,
        16384LL, 262144LL, 1048576LL, 0.f, 1.f, nullptr, nullptr, nullptr, nullptr);

    // 6. softmaxes (in place)
    softmax256_kernel<<<32768, 256>>>(g_attn1_p, 262144);
    softmax256_kernel<<<2048, 256>>>(g_attn2_p, 16384);
    softmax4096_kernel<<<16384, 256>>>(g_attn3_p);

    // 7. MP init: z0 = attn2^T / (max(rowsum)*max(colsum))
    mp_reset_kernel<<<1, 1>>>();
    mp_reduce_kernel<<<64, 256>>>(g_attn2_p);
    mp_init_kernel<<<16384, 256>>>(g_attn2_p, g_z0_p);

    // 8. 6 Newton-Schulz iterations (batched 256^3 GEMMs)
    float* zin = g_z0_p; float* zout = g_z1_p;
    for (int it = 0; it < 6; it++) {
        tgemm<false,false,false,false,false><<<dim3(4, 2, 64), 256, SMEM_BYTES>>>(
            g_attn2_p, zin, g_az_p, 256, 256, 256, 256,
            65536LL, 65536LL, 65536LL, 0.f, 1.f, nullptr, nullptr, nullptr, nullptr);
        tgemm<false,true,false,false,false><<<dim3(4, 2, 64), 256, SMEM_BYTES>>>(
            g_az_p, g_az_p, g_t2_p, 256, 256, 256, 256,
            65536LL, 65536LL, 65536LL, 7.f, 1.f, nullptr, nullptr, nullptr, nullptr);
        tgemm<false,true,false,false,false><<<dim3(4, 2, 64), 256, SMEM_BYTES>>>(
            g_az_p, g_t2_p, g_t4_p, 256, 256, 256, 256,
            65536LL, 65536LL, 65536LL, 15.f, 1.f, nullptr, nullptr, nullptr, nullptr);
        tgemm<false,true,false,false,false><<<dim3(4, 2, 64), 256, SMEM_BYTES>>>(
            zin, g_t4_p, zout, 256, 256, 256, 256,
            65536LL, 65536LL, 65536LL, 13.f, 0.25f, nullptr, nullptr, nullptr, nullptr);
        float* tmp = zin; zin = zout; zout = tmp;
    }

    // 9. a3v = attn3 @ V  [256,4096]@[4096,64], split-K x8 with atomic epilogue
    cudaMemsetAsync(g_a3v_p, 0, 1048576 * sizeof(float));
    tgemm<false,false,false,false,true><<<dim3(1, 2, 512), 256, SMEM_BYTES>>>(
        g_attn3_p, g_V_p, g_a3v_p, 512, 4096, 64, 64,
        1048576LL, 262144LL, 16384LL, 0.f, 1.f, nullptr, nullptr, nullptr, nullptr);

    // 10. tmp2 = z @ a3v   [256,256]@[256,64]
    tgemm<false,false,false,false,false><<<dim3(1, 2, 64), 256, SMEM_BYTES>>>(
        zin, g_a3v_p, g_tmp2_p, 256, 256, 64, 64,
        65536LL, 16384LL, 16384LL, 0.f, 1.f, nullptr, nullptr, nullptr, nullptr);

    // 11. out = attn1 @ tmp2   [4096,256]@[256,64]
    tgemm<false,false,false,false,false><<<dim3(1, 32, 64), 256, SMEM_BYTES>>>(
        g_attn1_p, g_tmp2_p, g_out_p, 256, 256, 64, 64,
        1048576LL, 16384LL, 262144LL, 0.f, 1.f, nullptr, nullptr, nullptr, nullptr);

    // 12. fused depthwise conv residual + transpose to [b,n,inner]
    conv_tr_kernel<<<65536, 256>>>(g_out_p, w_conv, g_outT_p);

    // 13. final fc: d_out = outT @ w_fc + b_fc   [16384,1024]@[1024,1024]
    tgemm<false,false,true,false,false><<<dim3(16, 128, 1), 256, SMEM_BYTES>>>(
        g_outT_p, w_fc, dout, 1024, 1024, 1024, 1024,
        0, 0, 0, 0.f, 1.f, b_fc, nullptr, nullptr, nullptr);
}

// round 7
// speedup vs baseline: 2.8002x; 1.1323x over previous
#include <cuda_runtime.h>
#include <cstdint>

// ============================================================================
// NystromAttention — tf32 tensor cores
//   tgemm2: CTA 128x128x32, warp 64x32 (large-N GEMMs, lower LDS/MAC)
//   tgemm : CTA 128x64x32,  warp 32x32 (N=64 tail GEMMs)
// Both double-buffered. Batched over b*h via grid.z.
// ============================================================================

// ---------------- scratch (device globals) ----------------------------------
__device__ float g_Q    [16777216];  // [b,h,n,d] scaled
__device__ float g_K    [16777216];
__device__ float g_V    [16777216];
__device__ float g_ql   [1048576];   // [bh, 256, 64]
__device__ float g_kl   [1048576];
__device__ float g_attn1[67108864];  // [bh, 4096, 256]
__device__ float g_attn3[67108864];  // [bh, 256, 4096]
__device__ float g_attn2[4194304];   // [bh, 256, 256]
__device__ float g_z0   [4194304];
__device__ float g_z1   [4194304];
__device__ float g_az   [4194304];
__device__ float g_t2   [4194304];
__device__ float g_t4   [4194304];
__device__ float g_a3v  [1048576];   // [bh, 256, 64]
__device__ float g_tmp2 [1048576];   // [bh, 256, 64]
__device__ float g_out  [16777216];  // [b,h,n,d]
__device__ float g_outT [16777216];  // [b,n,1024]
__device__ unsigned int g_m1, g_m2;

__device__ __forceinline__ unsigned f2tf(float f) {
    unsigned u;
    asm("cvt.rna.tf32.f32 %0, %1;" : "=r"(u) : "f"(f));
    return u;
}

#define MMA_TF32(acc, a0,a1,a2,a3, b0,b1)                                     \
    asm volatile(                                                             \
        "mma.sync.aligned.m16n8k8.row.col.f32.tf32.tf32.f32 "                 \
        "{%0,%1,%2,%3}, {%4,%5,%6,%7}, {%8,%9}, {%0,%1,%2,%3};"               \
        : "+f"(acc[0]), "+f"(acc[1]), "+f"(acc[2]), "+f"(acc[3])              \
        : "r"(a0), "r"(a1), "r"(a2), "r"(a3), "r"(b0), "r"(b1))

// ============================================================================
// tgemm2: CTA 128x128x32, 8 warps (2 row-groups x 4 col-groups), warp 64x32
// C = outScale * A @ Beff (+ bias); Beff = B (NN), B^T (NT), alpha*I - B (AIM)
// QKVE: scatter epilogue to Q/K/V in [b,h,n,d]
// ============================================================================
template<bool TRANSB, bool AIM, bool BIAS, bool QKVE>
__global__ __launch_bounds__(256)
void tgemm2(const float* __restrict__ A, const float* __restrict__ B,
            float* __restrict__ C, int Kdim, int lda, int ldb, int ldc,
            long long sA, long long sB, long long sC,
            float alpha, float outScale, const float* __restrict__ bias,
            float* __restrict__ qp, float* __restrict__ kp,
            float* __restrict__ vp)
{
    extern __shared__ unsigned sh[];
    unsigned* As = sh;                  // [2][128][36]
    unsigned* Bs = sh + 2 * 4608;       // [2][4608]  NN:[32][136] / NT:[128][36]

    const float* Ab = A + (long long)blockIdx.z * sA;
    const float* Bb = B + (long long)blockIdx.z * sB;
    float*       Cb = C + (long long)blockIdx.z * sC;

    const int row0 = blockIdx.y * 128;
    const int col0 = blockIdx.x * 128;
    const int t    = threadIdx.x;
    const int lane = t & 31;
    const int w    = t >> 5;
    const int wm   = w & 1;         // 2 row groups of 64
    const int wn   = w >> 1;        // 4 col groups of 32
    const int g    = lane >> 2;
    const int tg   = lane & 3;

    float4 aR[4], bR[4];

    auto ldA = [&](int k0) {
        #pragma unroll
        for (int l = 0; l < 4; l++) {
            int idx = t + l * 256;
            int r   = idx >> 3;
            int kq  = (idx & 7) << 2;
            aR[l] = *reinterpret_cast<const float4*>(
                Ab + (long long)(row0 + r) * lda + k0 + kq);
        }
    };
    auto stA = [&](int st) {
        unsigned* Ap = As + st * 4608;
        #pragma unroll
        for (int l = 0; l < 4; l++) {
            int idx = t + l * 256;
            int r   = idx >> 3;
            int kq  = (idx & 7) << 2;
            uint4 u = make_uint4(f2tf(aR[l].x), f2tf(aR[l].y),
                                 f2tf(aR[l].z), f2tf(aR[l].w));
            *reinterpret_cast<uint4*>(Ap + r * 36 + kq) = u;
        }
    };
    auto ldB = [&](int k0) {
        #pragma unroll
        for (int l = 0; l < 4; l++) {
            int idx = t + l * 256;
            if (!TRANSB) {
                int r  = idx >> 5;               // k 0..31
                int cq = (idx & 31) << 2;        // n 0..124
                bR[l] = *reinterpret_cast<const float4*>(
                    Bb + (long long)(k0 + r) * ldb + col0 + cq);
            } else {
                int j  = idx >> 3;               // n 0..127
                int kq = (idx & 7) << 2;
                bR[l] = *reinterpret_cast<const float4*>(
                    Bb + (long long)(col0 + j) * ldb + k0 + kq);
            }
        }
    };
    auto stB = [&](int st, int k0) {
        unsigned* Bp = Bs + st * 4608;
        #pragma unroll
        for (int l = 0; l < 4; l++) {
            int idx = t + l * 256;
            float4 bv = bR[l];
            if (!TRANSB) {
                int r  = idx >> 5;
                int cq = (idx & 31) << 2;
                if (AIM) {
                    int gk = k0 + r, gj = col0 + cq;
                    bv.x = ((gk == gj    ) ? alpha : 0.f) - bv.x;
                    bv.y = ((gk == gj + 1) ? alpha : 0.f) - bv.y;
                    bv.z = ((gk == gj + 2) ? alpha : 0.f) - bv.z;
                    bv.w = ((gk == gj + 3) ? alpha : 0.f) - bv.w;
                }
                uint4 u = make_uint4(f2tf(bv.x), f2tf(bv.y),
                                     f2tf(bv.z), f2tf(bv.w));
                *reinterpret_cast<uint4*>(Bp + r * 136 + cq) = u;
            } else {
                int j  = idx >> 3;
                int kq = (idx & 7) << 2;
                uint4 u = make_uint4(f2tf(bv.x), f2tf(bv.y),
                                     f2tf(bv.z), f2tf(bv.w));
                *reinterpret_cast<uint4*>(Bp + j * 36 + kq) = u;
            }
        }
    };

    float acc[4][4][4];
    #pragma unroll
    for (int mi = 0; mi < 4; mi++)
        #pragma unroll
        for (int ni = 0; ni < 4; ni++)
            #pragma unroll
            for (int q = 0; q < 4; q++) acc[mi][ni][q] = 0.f;

    ldA(0); ldB(0);
    stA(0); stB(0, 0);
    __syncthreads();

    int s = 0;
    for (int k0 = 0; k0 < Kdim; k0 += 32) {
        bool more = (k0 + 32 < Kdim);
        if (more) { ldA(k0 + 32); ldB(k0 + 32); }

        const unsigned* Ap = As + s * 4608;
        const unsigned* Bp = Bs + s * 4608;
        #pragma unroll
        for (int ks = 0; ks < 4; ks++) {
            const int kk = ks * 8;
            unsigned af[4][4], bf[4][2];
            #pragma unroll
            for (int mi = 0; mi < 4; mi++) {
                int rb = wm * 64 + mi * 16;
                af[mi][0] = Ap[(rb + g    ) * 36 + kk + tg];
                af[mi][1] = Ap[(rb + 8 + g) * 36 + kk + tg];
                af[mi][2] = Ap[(rb + g    ) * 36 + kk + 4 + tg];
                af[mi][3] = Ap[(rb + 8 + g) * 36 + kk + 4 + tg];
            }
            #pragma unroll
            for (int ni = 0; ni < 4; ni++) {
                int cb = wn * 32 + ni * 8;
                if (TRANSB) {
                    bf[ni][0] = Bp[(cb + g) * 36 + kk + tg];
                    bf[ni][1] = Bp[(cb + g) * 36 + kk + 4 + tg];
                } else {
                    bf[ni][0] = Bp[(kk + tg) * 136 + cb + g];
                    bf[ni][1] = Bp[(kk + 4 + tg) * 136 + cb + g];
                }
            }
            #pragma unroll
            for (int mi = 0; mi < 4; mi++)
                #pragma unroll
                for (int ni = 0; ni < 4; ni++)
                    MMA_TF32(acc[mi][ni],
                             af[mi][0], af[mi][1], af[mi][2], af[mi][3],
                             bf[ni][0], bf[ni][1]);
        }

        if (more) {
            stA(s ^ 1); stB(s ^ 1, k0 + 32);
            __syncthreads();
        }
        s ^= 1;
    }

    #pragma unroll
    for (int mi = 0; mi < 4; mi++) {
        int r = row0 + wm * 64 + mi * 16 + g;
        #pragma unroll
        for (int ni = 0; ni < 4; ni++) {
            int c = col0 + wn * 32 + ni * 8 + 2 * tg;
            if (QKVE) {
                int which = c >> 10, hh = (c >> 6) & 15, d = c & 63;
                float sc = (which == 0) ? 0.125f : 1.f;
                float* dst = (which == 0) ? qp : ((which == 1) ? kp : vp);
                long long base =
                    (((long long)((r >> 12) * 16 + hh)) * 4096 + (r & 4095)) * 64 + d;
                *reinterpret_cast<float2*>(dst + base) =
                    make_float2(acc[mi][ni][0] * sc, acc[mi][ni][1] * sc);
                *reinterpret_cast<float2*>(dst + base + 512) =
                    make_float2(acc[mi][ni][2] * sc, acc[mi][ni][3] * sc);
            } else {
                float b0 = 0.f, b1 = 0.f;
                if (BIAS) { b0 = bias[c]; b1 = bias[c + 1]; }
                float2 o0 = make_float2(acc[mi][ni][0] * outScale + b0,
                                        acc[mi][ni][1] * outScale + b1);
                float2 o1 = make_float2(acc[mi][ni][2] * outScale + b0,
                                        acc[mi][ni][3] * outScale + b1);
                *reinterpret_cast<float2*>(Cb + (long long)r * ldc + c)       = o0;
                *reinterpret_cast<float2*>(Cb + (long long)(r + 8) * ldc + c) = o1;
            }
        }
    }
}

// ============================================================================
// tgemm: CTA 128x64x32, 8 warps (4x2), warp 32x32 — for N=64 tail GEMMs
// SPLITK: grid.z = bh*8+ks; atomicAdd epilogue (C pre-zeroed)
// ============================================================================
template<bool SPLITK>
__global__ __launch_bounds__(256)
void tgemm(const float* __restrict__ A, const float* __restrict__ B,
           float* __restrict__ C, int Kdim, int lda, int ldb, int ldc,
           long long sA, long long sB, long long sC)
{
    extern __shared__ unsigned sh[];
    unsigned* As = sh;                 // [2][128][36]
    unsigned* Bs = sh + 2 * 4608;      // [2][32][72]  (NN only)

    const float* Ab;
    const float* Bb;
    float*       Cb;
    if (SPLITK) {
        int bh = blockIdx.z >> 3, ks = blockIdx.z & 7;
        Ab = A + (long long)bh * sA + (long long)ks * Kdim;
        Bb = B + (long long)bh * sB + (long long)ks * Kdim * ldb;
        Cb = C + (long long)bh * sC;
    } else {
        Ab = A + (long long)blockIdx.z * sA;
        Bb = B + (long long)blockIdx.z * sB;
        Cb = C + (long long)blockIdx.z * sC;
    }

    const int row0 = blockIdx.y * 128;
    const int col0 = blockIdx.x * 64;
    const int t    = threadIdx.x;
    const int lane = t & 31;
    const int w    = t >> 5;
    const int wm   = w & 3;
    const int wn   = w >> 2;
    const int g    = lane >> 2;
    const int tg   = lane & 3;

    float4 aR[4];
    float4 bR[2];

    auto ldA = [&](int k0) {
        #pragma unroll
        for (int l = 0; l < 4; l++) {
            int idx = t + l * 256;
            int r   = idx >> 3;
            int kq  = (idx & 7) << 2;
            aR[l] = *reinterpret_cast<const float4*>(
                Ab + (long long)(row0 + r) * lda + k0 + kq);
        }
    };
    auto stA = [&](int st) {
        unsigned* Ap = As + st * 4608;
        #pragma unroll
        for (int l = 0; l < 4; l++) {
            int idx = t + l * 256;
            int r   = idx >> 3;
            int kq  = (idx & 7) << 2;
            uint4 u = make_uint4(f2tf(aR[l].x), f2tf(aR[l].y),
                                 f2tf(aR[l].z), f2tf(aR[l].w));
            *reinterpret_cast<uint4*>(Ap + r * 36 + kq) = u;
        }
    };
    auto ldB = [&](int k0) {
        #pragma unroll
        for (int l = 0; l < 2; l++) {
            int idx = t + l * 256;
            int r  = idx >> 4;
            int cq = (idx & 15) << 2;
            bR[l] = *reinterpret_cast<const float4*>(
                Bb + (long long)(k0 + r) * ldb + col0 + cq);
        }
    };
    auto stB = [&](int st) {
        unsigned* Bp = Bs + st * 2304;
        #pragma unroll
        for (int l = 0; l < 2; l++) {
            int idx = t + l * 256;
            int r  = idx >> 4;
            int cq = (idx & 15) << 2;
            uint4 u = make_uint4(f2tf(bR[l].x), f2tf(bR[l].y),
                                 f2tf(bR[l].z), f2tf(bR[l].w));
            *reinterpret_cast<uint4*>(Bp + r * 72 + cq) = u;
        }
    };

    float acc[2][4][4];
    #pragma unroll
    for (int mi = 0; mi < 2; mi++)
        #pragma unroll
        for (int ni = 0; ni < 4; ni++)
            #pragma unroll
            for (int q = 0; q < 4; q++) acc[mi][ni][q] = 0.f;

    ldA(0); ldB(0);
    stA(0); stB(0);
    __syncthreads();

    int s = 0;
    for (int k0 = 0; k0 < Kdim; k0 += 32) {
        bool more = (k0 + 32 < Kdim);
        if (more) { ldA(k0 + 32); ldB(k0 + 32); }

        const unsigned* Ap = As + s * 4608;
        const unsigned* Bp = Bs + s * 2304;
        #pragma unroll
        for (int ks = 0; ks < 4; ks++) {
            const int kk = ks * 8;
            unsigned af[2][4], bf[4][2];
            #pragma unroll
            for (int mi = 0; mi < 2; mi++) {
                int rb = wm * 32 + mi * 16;
                af[mi][0] = Ap[(rb + g    ) * 36 + kk + tg];
                af[mi][1] = Ap[(rb + 8 + g) * 36 + kk + tg];
                af[mi][2] = Ap[(rb + g    ) * 36 + kk + 4 + tg];
                af[mi][3] = Ap[(rb + 8 + g) * 36 + kk + 4 + tg];
            }
            #pragma unroll
            for (int ni = 0; ni < 4; ni++) {
                int cb = wn * 32 + ni * 8;
                bf[ni][0] = Bp[(kk + tg) * 72 + cb + g];
                bf[ni][1] = Bp[(kk + 4 + tg) * 72 + cb + g];
            }
            #pragma unroll
            for (int mi = 0; mi < 2; mi++)
                #pragma unroll
                for (int ni = 0; ni < 4; ni++)
                    MMA_TF32(acc[mi][ni],
                             af[mi][0], af[mi][1], af[mi][2], af[mi][3],
                             bf[ni][0], bf[ni][1]);
        }

        if (more) {
            stA(s ^ 1); stB(s ^ 1);
            __syncthreads();
        }
        s ^= 1;
    }

    #pragma unroll
    for (int mi = 0; mi < 2; mi++) {
        int r = row0 + wm * 32 + mi * 16 + g;
        #pragma unroll
        for (int ni = 0; ni < 4; ni++) {
            int c = col0 + wn * 32 + ni * 8 + 2 * tg;
            if (SPLITK) {
                float* p0 = Cb + (long long)r * ldc + c;
                atomicAdd(p0,                          acc[mi][ni][0]);
                atomicAdd(p0 + 1,                      acc[mi][ni][1]);
                atomicAdd(p0 + (long long)8 * ldc,     acc[mi][ni][2]);
                atomicAdd(p0 + (long long)8 * ldc + 1, acc[mi][ni][3]);
            } else {
                *reinterpret_cast<float2*>(Cb + (long long)r * ldc + c) =
                    make_float2(acc[mi][ni][0], acc[mi][ni][1]);
                *reinterpret_cast<float2*>(Cb + (long long)(r + 8) * ldc + c) =
                    make_float2(acc[mi][ni][2], acc[mi][ni][3]);
            }
        }
    }
}

// ---------------- elementwise / reductions ---------------------------------
__global__ void landmarks_kernel(const float* __restrict__ Q,
                                 const float* __restrict__ K,
                                 float* __restrict__ ql, float* __restrict__ kl)
{
    int i = blockIdx.x * 256 + threadIdx.x;
    int d = i & 63;
    int m = (i >> 6) & 255;
    int bh = i >> 14;
    long long base = ((long long)bh * 4096 + m * 16) * 64 + d;
    float sq = 0.f, sk = 0.f;
    #pragma unroll
    for (int j = 0; j < 16; j++) {
        sq += Q[base + j * 64];
        sk += K[base + j * 64];
    }
    ql[i] = sq * 0.0625f;
    kl[i] = sk * 0.0625f;
}

__global__ void softmax256_kernel(float* __restrict__ data, int rows)
{
    int gw   = (int)((blockIdx.x * (long long)blockDim.x + threadIdx.x) >> 5);
    int lane = threadIdx.x & 31;
    if (gw >= rows) return;
    float* p = data + (long long)gw * 256;
    float v[8];
    float mx = -1e30f;
    #pragma unroll
    for (int i = 0; i < 8; i++) { v[i] = p[lane + 32 * i]; mx = fmaxf(mx, v[i]); }
    #pragma unroll
    for (int o = 16; o > 0; o >>= 1) mx = fmaxf(mx, __shfl_xor_sync(0xffffffffu, mx, o));
    float s = 0.f;
    #pragma unroll
    for (int i = 0; i < 8; i++) { v[i] = expf(v[i] - mx); s += v[i]; }
    #pragma unroll
    for (int o = 16; o > 0; o >>= 1) s += __shfl_xor_sync(0xffffffffu, s, o);
    float inv = 1.f / s;
    #pragma unroll
    for (int i = 0; i < 8; i++) p[lane + 32 * i] = v[i] * inv;
}

__global__ void softmax4096_kernel(float* __restrict__ data)
{
    float* p = data + (long long)blockIdx.x * 4096;
    int t = threadIdx.x;
    float v[16];
    float mx = -1e30f;
    #pragma unroll
    for (int i = 0; i < 16; i++) { v[i] = p[t + 256 * i]; mx = fmaxf(mx, v[i]); }
    __shared__ float red[256];
    red[t] = mx; __syncthreads();
    for (int s = 128; s > 0; s >>= 1) {
        if (t < s) red[t] = fmaxf(red[t], red[t + s]);
        __syncthreads();
    }
    mx = red[0]; __syncthreads();
    float sum = 0.f;
    #pragma unroll
    for (int i = 0; i < 16; i++) { v[i] = expf(v[i] - mx); sum += v[i]; }
    red[t] = sum; __syncthreads();
    for (int s = 128; s > 0; s >>= 1) {
        if (t < s) red[t] += red[t + s];
        __syncthreads();
    }
    float inv = 1.f / red[0];
    #pragma unroll
    for (int i = 0; i < 16; i++) p[t + 256 * i] = v[i] * inv;
}

__global__ void mp_reset_kernel() { g_m1 = 0u; g_m2 = 0u; }

__global__ void mp_reduce_kernel(const float* __restrict__ a)
{
    int bh = blockIdx.x;
    int j  = threadIdx.x;
    const float* p = a + (long long)bh * 65536;
    float rs = 0.f, cs = 0.f;
    for (int i = 0; i < 256; i++) {
        rs += fabsf(p[j * 256 + i]);
        cs += fabsf(p[i * 256 + j]);
    }
    __shared__ float r1[256], r2[256];
    r1[j] = rs; r2[j] = cs; __syncthreads();
    for (int s = 128; s > 0; s >>= 1) {
        if (j < s) { r1[j] = fmaxf(r1[j], r1[j + s]); r2[j] = fmaxf(r2[j], r2[j + s]); }
        __syncthreads();
    }
    if (j == 0) {
        atomicMax(&g_m1, __float_as_uint(r1[0]));
        atomicMax(&g_m2, __float_as_uint(r2[0]));
    }
}

__global__ void mp_init_kernel(const float* __restrict__ a, float* __restrict__ z)
{
    long long i = (long long)blockIdx.x * 256 + threadIdx.x;
    int col = (int)(i & 255);
    int row = (int)((i >> 8) & 255);
    long long bh = i >> 16;
    float denom = __uint_as_float(g_m1) * __uint_as_float(g_m2);
    z[i] = a[bh * 65536 + (long long)col * 256 + row] / denom;
}

// fused: depthwise residual conv (K=13, pad 6) + [b,h,n,d] -> [b,n,h*64+d]
__global__ void conv_tr_kernel(const float* __restrict__ src,
                               const float* __restrict__ w,
                               float* __restrict__ dst)
{
    long long o = (long long)blockIdx.x * 256 + threadIdx.x;
    int d = (int)(o & 63);
    int h = (int)((o >> 6) & 15);
    int n = (int)((o >> 10) & 4095);
    int b = (int)(o >> 22);
    long long s = (((long long)(b * 16 + h)) * 4096 + n) * 64 + d;
    float v = src[s];
    float r = 0.f;
    #pragma unroll
    for (int tt = 0; tt < 13; tt++) {
        int nn = n + tt - 6;
        if (nn >= 0 && nn < 4096)
            r += w[h * 13 + tt] * src[s + (long long)(tt - 6) * 64];
    }
    dst[o] = v + r;
}

// ---------------- launch ----------------------------------------------------
static constexpr int SMEM1 = (2 * 4608 + 2 * 2304) * 4;  // 55296 (tgemm)
static constexpr int SMEM2 = (4 * 4608) * 4;             // 73728 (tgemm2)

extern "C" void kernel_launch(void* const* d_in, const int* in_sizes, int n_in,
                              void* d_out, int out_size)
{
    (void)in_sizes; (void)n_in; (void)out_size;
    const float* x      = (const float*)d_in[0];
    const float* w_qkv  = (const float*)d_in[1];
    const float* w_conv = (const float*)d_in[2];
    const float* w_fc   = (const float*)d_in[3];
    const float* b_fc   = (const float*)d_in[4];
    float* dout = (float*)d_out;

    void* vp_;
    #define SYMP(nm) float* nm##_p; cudaGetSymbolAddress(&vp_, nm); nm##_p = (float*)vp_;
    SYMP(g_Q)    SYMP(g_K)    SYMP(g_V)
    SYMP(g_ql)   SYMP(g_kl)
    SYMP(g_attn1) SYMP(g_attn3) SYMP(g_attn2)
    SYMP(g_z0)   SYMP(g_z1)   SYMP(g_az)   SYMP(g_t2) SYMP(g_t4)
    SYMP(g_a3v)  SYMP(g_tmp2)
    SYMP(g_out)  SYMP(g_outT)
    #undef SYMP

    cudaFuncSetAttribute(tgemm2<false,false,false,true >,
                         cudaFuncAttributeMaxDynamicSharedMemorySize, SMEM2);
    cudaFuncSetAttribute(tgemm2<true ,false,false,false>,
                         cudaFuncAttributeMaxDynamicSharedMemorySize, SMEM2);
    cudaFuncSetAttribute(tgemm2<false,false,false,false>,
                         cudaFuncAttributeMaxDynamicSharedMemorySize, SMEM2);
    cudaFuncSetAttribute(tgemm2<false,true ,false,false>,
                         cudaFuncAttributeMaxDynamicSharedMemorySize, SMEM2);
    cudaFuncSetAttribute(tgemm2<false,false,true ,false>,
                         cudaFuncAttributeMaxDynamicSharedMemorySize, SMEM2);
    cudaFuncSetAttribute(tgemm<false>,
                         cudaFuncAttributeMaxDynamicSharedMemorySize, SMEM1);
    cudaFuncSetAttribute(tgemm<true>,
                         cudaFuncAttributeMaxDynamicSharedMemorySize, SMEM1);

    // 1. qkv projection fused with split+scale -> g_Q/g_K/g_V
    tgemm2<false,false,false,true><<<dim3(24, 128, 1), 256, SMEM2>>>(
        x, w_qkv, nullptr, 1024, 1024, 3072, 0, 0, 0, 0, 0.f, 1.f, nullptr,
        g_Q_p, g_K_p, g_V_p);

    // 2. landmarks
    landmarks_kernel<<<4096, 256>>>(g_Q_p, g_K_p, g_ql_p, g_kl_p);

    // 3. sim1 = Q @ kl^T   [4096,64]@[256,64]^T  (batch 64)
    tgemm2<true,false,false,false><<<dim3(2, 32, 64), 256, SMEM2>>>(
        g_Q_p, g_kl_p, g_attn1_p, 64, 64, 64, 256,
        262144LL, 16384LL, 1048576LL, 0.f, 1.f, nullptr, nullptr, nullptr, nullptr);

    // 4. sim2 = ql @ kl^T  [256,64]@[256,64]^T
    tgemm2<true,false,false,false><<<dim3(2, 2, 64), 256, SMEM2>>>(
        g_ql_p, g_kl_p, g_attn2_p, 64, 64, 64, 256,
        16384LL, 16384LL, 65536LL, 0.f, 1.f, nullptr, nullptr, nullptr, nullptr);

    // 5. sim3 = ql @ K^T   [256,64]@[4096,64]^T
    tgemm2<true,false,false,false><<<dim3(32, 2, 64), 256, SMEM2>>>(
        g_ql_p, g_K_p, g_attn3_p, 64, 64, 64, 4096,
        16384LL, 262144LL, 1048576LL, 0.f, 1.f, nullptr, nullptr, nullptr, nullptr);

    // 6. softmaxes (in place)
    softmax256_kernel<<<32768, 256>>>(g_attn1_p, 262144);
    softmax256_kernel<<<2048, 256>>>(g_attn2_p, 16384);
    softmax4096_kernel<<<16384, 256>>>(g_attn3_p);

    // 7. MP init
    mp_reset_kernel<<<1, 1>>>();
    mp_reduce_kernel<<<64, 256>>>(g_attn2_p);
    mp_init_kernel<<<16384, 256>>>(g_attn2_p, g_z0_p);

    // 8. 6 Newton-Schulz iterations
    float* zin = g_z0_p; float* zout = g_z1_p;
    for (int it = 0; it < 6; it++) {
        tgemm2<false,false,false,false><<<dim3(2, 2, 64), 256, SMEM2>>>(
            g_attn2_p, zin, g_az_p, 256, 256, 256, 256,
            65536LL, 65536LL, 65536LL, 0.f, 1.f, nullptr, nullptr, nullptr, nullptr);
        tgemm2<false,true,false,false><<<dim3(2, 2, 64), 256, SMEM2>>>(
            g_az_p, g_az_p, g_t2_p, 256, 256, 256, 256,
            65536LL, 65536LL, 65536LL, 7.f, 1.f, nullptr, nullptr, nullptr, nullptr);
        tgemm2<false,true,false,false><<<dim3(2, 2, 64), 256, SMEM2>>>(
            g_az_p, g_t2_p, g_t4_p, 256, 256, 256, 256,
            65536LL, 65536LL, 65536LL, 15.f, 1.f, nullptr, nullptr, nullptr, nullptr);
        tgemm2<false,true,false,false><<<dim3(2, 2, 64), 256, SMEM2>>>(
            zin, g_t4_p, zout, 256, 256, 256, 256,
            65536LL, 65536LL, 65536LL, 13.f, 0.25f, nullptr, nullptr, nullptr, nullptr);
        float* tmp = zin; zin = zout; zout = tmp;
    }

    // 9. a3v = attn3 @ V  [256,4096]@[4096,64], split-K x8 atomic epilogue
    cudaMemsetAsync(g_a3v_p, 0, 1048576 * sizeof(float));
    tgemm<true><<<dim3(1, 2, 512), 256, SMEM1>>>(
        g_attn3_p, g_V_p, g_a3v_p, 512, 4096, 64, 64,
        1048576LL, 262144LL, 16384LL);

    // 10. tmp2 = z @ a3v   [256,256]@[256,64]
    tgemm<false><<<dim3(1, 2, 64), 256, SMEM1>>>(
        zin, g_a3v_p, g_tmp2_p, 256, 256, 64, 64,
        65536LL, 16384LL, 16384LL);

    // 11. out = attn1 @ tmp2   [4096,256]@[256,64]
    tgemm<false><<<dim3(1, 32, 64), 256, SMEM1>>>(
        g_attn1_p, g_tmp2_p, g_out_p, 256, 256, 64, 64,
        1048576LL, 16384LL, 262144LL);

    // 12. fused depthwise conv residual + transpose to [b,n,inner]
    conv_tr_kernel<<<65536, 256>>>(g_out_p, w_conv, g_outT_p);

    // 13. final fc: d_out = outT @ w_fc + b_fc   [16384,1024]@[1024,1024]
    tgemm2<false,false,true,false><<<dim3(8, 128, 1), 256, SMEM2>>>(
        g_outT_p, w_fc, dout, 1024, 1024, 1024, 1024,
        0, 0, 0, 0.f, 1.f, b_fc, nullptr, nullptr, nullptr);
}

// round 8
// speedup vs baseline: 3.1891x; 1.1389x over previous
#include <cuda_runtime.h>
#include <cstdint>

// ============================================================================
// NystromAttention — tf32 tensor cores, cp.async operand pipeline
//   tgemm3: CTA 128x128x32, 4 warps (2x2) of 64x64, cp.async, 2 CTAs/SM
//   tgemm : CTA 128x64x32 (N=64 tails, LDG+cvt path)
// All GEMM inputs are pre-rounded to tf32 by producers, so mma's hardware
// truncation is exact and cp.async can feed smem directly (no cvt, no staging).
// ============================================================================

// ---------------- scratch (device globals) ----------------------------------
__device__ float g_xr   [16777216];  // tf32-rounded x
__device__ float g_wqkvr[3145728];   // tf32-rounded w_qkv
__device__ float g_wfcr [1048576];   // tf32-rounded w_fc
__device__ float g_Q    [16777216];  // [b,h,n,d] scaled, rounded
__device__ float g_K    [16777216];
__device__ float g_V    [16777216];
__device__ float g_ql   [1048576];   // [bh, 256, 64]
__device__ float g_kl   [1048576];
__device__ float g_attn1[67108864];  // [bh, 4096, 256]
__device__ float g_attn3[67108864];  // [bh, 256, 4096]
__device__ float g_attn2[4194304];   // [bh, 256, 256]
__device__ float g_z0   [4194304];
__device__ float g_z1   [4194304];
__device__ float g_az   [4194304];
__device__ float g_t2   [4194304];
__device__ float g_t4   [4194304];
__device__ float g_a3v  [1048576];   // [bh, 256, 64]
__device__ float g_tmp2 [1048576];   // [bh, 256, 64]
__device__ float g_out  [16777216];  // [b,h,n,d]
__device__ float g_outT [16777216];  // [b,n,1024]
__device__ unsigned int g_m1, g_m2;

__device__ __forceinline__ unsigned f2tf(float f) {
    unsigned u;
    asm("cvt.rna.tf32.f32 %0, %1;" : "=r"(u) : "f"(f));
    return u;
}
__device__ __forceinline__ float rndtf(float f) {
    return __uint_as_float(f2tf(f));
}
__device__ __forceinline__ void cp16(unsigned d, const void* s) {
    asm volatile("cp.async.cg.shared.global [%0], [%1], 16;"
                 :: "r"(d), "l"(s) : "memory");
}
#define CP_COMMIT() asm volatile("cp.async.commit_group;" ::: "memory")
#define CP_WAIT0()  asm volatile("cp.async.wait_group 0;" ::: "memory")
#define CP_WAIT1()  asm volatile("cp.async.wait_group 1;" ::: "memory")

#define MMA_TF32(acc, a0,a1,a2,a3, b0,b1)                                     \
    asm volatile(                                                             \
        "mma.sync.aligned.m16n8k8.row.col.f32.tf32.tf32.f32 "                 \
        "{%0,%1,%2,%3}, {%4,%5,%6,%7}, {%8,%9}, {%0,%1,%2,%3};"               \
        : "+f"(acc[0]), "+f"(acc[1]), "+f"(acc[2]), "+f"(acc[3])              \
        : "r"(a0), "r"(a1), "r"(a2), "r"(a3), "r"(b0), "r"(b1))

// ============================================================================
// tgemm3: CTA 128x128x32, 4 warps (2x2), warp 64x64, cp.async double buffer.
// Inputs MUST be tf32-pre-rounded fp32.
// EPI:  out = (alpha*E[r,c] - acc) * outScale   (Newton-Schulz fused form)
// QKVE: scatter epilogue to Q/K/V in [b,h,n,d] with q-scale + rounding
// RND:  round output to tf32
// ============================================================================
static constexpr int AW = 128 * 36;   // A stage words
static constexpr int BW_NN = 32 * 136;
static constexpr int BW_NT = 128 * 36;
static constexpr int SMEM3 = (2 * AW + 2 * BW_NT) * 4;  // 73728 (max of NN/NT)

template<bool TRANSB, bool EPI, bool BIAS, bool QKVE, bool RND>
__global__ __launch_bounds__(128)
void tgemm3(const float* __restrict__ A, const float* __restrict__ B,
            float* __restrict__ C, const float* __restrict__ E,
            int Kdim, int lda, int ldb, int ldc,
            long long sA, long long sB, long long sC,
            float alpha, float outScale, const float* __restrict__ bias,
            float* __restrict__ qp, float* __restrict__ kp,
            float* __restrict__ vp)
{
    constexpr int BW = TRANSB ? BW_NT : BW_NN;
    extern __shared__ unsigned sh[];
    unsigned* Ash = sh;               // [2][128][36]
    unsigned* Bsh = sh + 2 * AW;      // [2][BW]

    const float* Ab = A + (long long)blockIdx.z * sA;
    const float* Bb = B + (long long)blockIdx.z * sB;
    float*       Cb = C + (long long)blockIdx.z * sC;
    const float* Eb = EPI ? (E + (long long)blockIdx.z * sC) : nullptr;

    const int row0 = blockIdx.y * 128;
    const int col0 = blockIdx.x * 128;
    const int t    = threadIdx.x;
    const int lane = t & 31;
    const int w    = t >> 5;
    const int wm   = w & 1;          // 2 row groups of 64
    const int wn   = w >> 1;         // 2 col groups of 64
    const int g    = lane >> 2;
    const int tg   = lane & 3;

    const unsigned aBase = (unsigned)__cvta_generic_to_shared(Ash);
    const unsigned bBase = (unsigned)__cvta_generic_to_shared(Bsh);

    auto issue = [&](int k0, int st) {
        // A tile: 128x32 floats = 1024 x 16B chunks, 8 per thread
        unsigned ab = aBase + st * (AW * 4);
        #pragma unroll
        for (int l = 0; l < 8; l++) {
            int c  = t + l * 128;
            int r  = c >> 3;
            int kq = (c & 7) << 2;
            cp16(ab + (unsigned)(r * 36 + kq) * 4,
                 Ab + (long long)(row0 + r) * lda + k0 + kq);
        }
        unsigned bb = bBase + st * (BW * 4);
        #pragma unroll
        for (int l = 0; l < 8; l++) {
            int c = t + l * 128;
            if (!TRANSB) {
                int k  = c >> 5;
                int n4 = (c & 31) << 2;
                cp16(bb + (unsigned)(k * 136 + n4) * 4,
                     Bb + (long long)(k0 + k) * ldb + col0 + n4);
            } else {
                int j  = c >> 3;
                int kq = (c & 7) << 2;
                cp16(bb + (unsigned)(j * 36 + kq) * 4,
                     Bb + (long long)(col0 + j) * ldb + k0 + kq);
            }
        }
        CP_COMMIT();
    };

    float acc[4][8][4];
    #pragma unroll
    for (int mi = 0; mi < 4; mi++)
        #pragma unroll
        for (int ni = 0; ni < 8; ni++)
            #pragma unroll
            for (int q = 0; q < 4; q++) acc[mi][ni][q] = 0.f;

    issue(0, 0);

    int si = 0;
    for (int k0 = 0; k0 < Kdim; k0 += 32) {
        bool more = (k0 + 32 < Kdim);
        if (more) { issue(k0 + 32, si ^ 1); CP_WAIT1(); }
        else      { CP_WAIT0(); }
        __syncthreads();

        const unsigned* Ap = Ash + si * AW;
        const unsigned* Bp = Bsh + si * BW;
        #pragma unroll
        for (int ks = 0; ks < 4; ks++) {
            const int kk = ks * 8;
            unsigned af[4][4], bf[8][2];
            #pragma unroll
            for (int mi = 0; mi < 4; mi++) {
                int rb = wm * 64 + mi * 16;
                af[mi][0] = Ap[(rb + g    ) * 36 + kk + tg];
                af[mi][1] = Ap[(rb + 8 + g) * 36 + kk + tg];
                af[mi][2] = Ap[(rb + g    ) * 36 + kk + 4 + tg];
                af[mi][3] = Ap[(rb + 8 + g) * 36 + kk + 4 + tg];
            }
            #pragma unroll
            for (int ni = 0; ni < 8; ni++) {
                int cb = wn * 64 + ni * 8;
                if (TRANSB) {
                    bf[ni][0] = Bp[(cb + g) * 36 + kk + tg];
                    bf[ni][1] = Bp[(cb + g) * 36 + kk + 4 + tg];
                } else {
                    bf[ni][0] = Bp[(kk + tg) * 136 + cb + g];
                    bf[ni][1] = Bp[(kk + 4 + tg) * 136 + cb + g];
                }
            }
            #pragma unroll
            for (int mi = 0; mi < 4; mi++)
                #pragma unroll
                for (int ni = 0; ni < 8; ni++)
                    MMA_TF32(acc[mi][ni],
                             af[mi][0], af[mi][1], af[mi][2], af[mi][3],
                             bf[ni][0], bf[ni][1]);
        }
        __syncthreads();
        si ^= 1;
    }

    // ---- epilogue
    #pragma unroll
    for (int mi = 0; mi < 4; mi++) {
        int r = row0 + wm * 64 + mi * 16 + g;
        #pragma unroll
        for (int ni = 0; ni < 8; ni++) {
            int c = col0 + wn * 64 + ni * 8 + 2 * tg;
            float v00 = acc[mi][ni][0], v01 = acc[mi][ni][1];
            float v10 = acc[mi][ni][2], v11 = acc[mi][ni][3];
            if (QKVE) {
                int which = c >> 10, hh = (c >> 6) & 15, d = c & 63;
                float sc = (which == 0) ? 0.125f : 1.f;
                float* dst = (which == 0) ? qp : ((which == 1) ? kp : vp);
                long long base =
                    (((long long)((r >> 12) * 16 + hh)) * 4096 + (r & 4095)) * 64 + d;
                *reinterpret_cast<float2*>(dst + base) =
                    make_float2(rndtf(v00 * sc), rndtf(v01 * sc));
                *reinterpret_cast<float2*>(dst + base + 512) =
                    make_float2(rndtf(v10 * sc), rndtf(v11 * sc));
                continue;
            }
            if (EPI) {
                float2 e0 = *reinterpret_cast<const float2*>(
                    Eb + (long long)r * ldc + c);
                float2 e1 = *reinterpret_cast<const float2*>(
                    Eb + (long long)(r + 8) * ldc + c);
                v00 = (alpha * e0.x - v00) * outScale;
                v01 = (alpha * e0.y - v01) * outScale;
                v10 = (alpha * e1.x - v10) * outScale;
                v11 = (alpha * e1.y - v11) * outScale;
            } else {
                float b0 = 0.f, b1 = 0.f;
                if (BIAS) { b0 = bias[c]; b1 = bias[c + 1]; }
                v00 = v00 * outScale + b0;  v01 = v01 * outScale + b1;
                v10 = v10 * outScale + b0;  v11 = v11 * outScale + b1;
            }
            if (RND) {
                v00 = rndtf(v00); v01 = rndtf(v01);
                v10 = rndtf(v10); v11 = rndtf(v11);
            }
            *reinterpret_cast<float2*>(Cb + (long long)r * ldc + c) =
                make_float2(v00, v01);
            *reinterpret_cast<float2*>(Cb + (long long)(r + 8) * ldc + c) =
                make_float2(v10, v11);
        }
    }
}

// ============================================================================
// tgemm: CTA 128x64x32, 8 warps (4x2), warp 32x32 — N=64 tails (LDG+cvt path)
// SPLITK: grid.z = bh*8+ks; atomicAdd epilogue (C pre-zeroed)
// ============================================================================
template<bool SPLITK>
__global__ __launch_bounds__(256)
void tgemm(const float* __restrict__ A, const float* __restrict__ B,
           float* __restrict__ C, int Kdim, int lda, int ldb, int ldc,
           long long sA, long long sB, long long sC)
{
    extern __shared__ unsigned sh[];
    unsigned* As = sh;                 // [2][128][36]
    unsigned* Bs = sh + 2 * 4608;      // [2][32][72]

    const float* Ab;
    const float* Bb;
    float*       Cb;
    if (SPLITK) {
        int bh = blockIdx.z >> 3, ks = blockIdx.z & 7;
        Ab = A + (long long)bh * sA + (long long)ks * Kdim;
        Bb = B + (long long)bh * sB + (long long)ks * Kdim * ldb;
        Cb = C + (long long)bh * sC;
    } else {
        Ab = A + (long long)blockIdx.z * sA;
        Bb = B + (long long)blockIdx.z * sB;
        Cb = C + (long long)blockIdx.z * sC;
    }

    const int row0 = blockIdx.y * 128;
    const int col0 = blockIdx.x * 64;
    const int t    = threadIdx.x;
    const int lane = t & 31;
    const int w    = t >> 5;
    const int wm   = w & 3;
    const int wn   = w >> 2;
    const int g    = lane >> 2;
    const int tg   = lane & 3;

    float4 aR[4];
    float4 bR[2];

    auto ldA = [&](int k0) {
        #pragma unroll
        for (int l = 0; l < 4; l++) {
            int idx = t + l * 256;
            int r   = idx >> 3;
            int kq  = (idx & 7) << 2;
            aR[l] = *reinterpret_cast<const float4*>(
                Ab + (long long)(row0 + r) * lda + k0 + kq);
        }
    };
    auto stA = [&](int st) {
        unsigned* Ap = As + st * 4608;
        #pragma unroll
        for (int l = 0; l < 4; l++) {
            int idx = t + l * 256;
            int r   = idx >> 3;
            int kq  = (idx & 7) << 2;
            uint4 u = make_uint4(f2tf(aR[l].x), f2tf(aR[l].y),
                                 f2tf(aR[l].z), f2tf(aR[l].w));
            *reinterpret_cast<uint4*>(Ap + r * 36 + kq) = u;
        }
    };
    auto ldB = [&](int k0) {
        #pragma unroll
        for (int l = 0; l < 2; l++) {
            int idx = t + l * 256;
            int r  = idx >> 4;
            int cq = (idx & 15) << 2;
            bR[l] = *reinterpret_cast<const float4*>(
                Bb + (long long)(k0 + r) * ldb + col0 + cq);
        }
    };
    auto stB = [&](int st) {
        unsigned* Bp = Bs + st * 2304;
        #pragma unroll
        for (int l = 0; l < 2; l++) {
            int idx = t + l * 256;
            int r  = idx >> 4;
            int cq = (idx & 15) << 2;
            uint4 u = make_uint4(f2tf(bR[l].x), f2tf(bR[l].y),
                                 f2tf(bR[l].z), f2tf(bR[l].w));
            *reinterpret_cast<uint4*>(Bp + r * 72 + cq) = u;
        }
    };

    float acc[2][4][4];
    #pragma unroll
    for (int mi = 0; mi < 2; mi++)
        #pragma unroll
        for (int ni = 0; ni < 4; ni++)
            #pragma unroll
            for (int q = 0; q < 4; q++) acc[mi][ni][q] = 0.f;

    ldA(0); ldB(0);
    stA(0); stB(0);
    __syncthreads();

    int s = 0;
    for (int k0 = 0; k0 < Kdim; k0 += 32) {
        bool more = (k0 + 32 < Kdim);
        if (more) { ldA(k0 + 32); ldB(k0 + 32); }

        const unsigned* Ap = As + s * 4608;
        const unsigned* Bp = Bs + s * 2304;
        #pragma unroll
        for (int ks = 0; ks < 4; ks++) {
            const int kk = ks * 8;
            unsigned af[2][4], bf[4][2];
            #pragma unroll
            for (int mi = 0; mi < 2; mi++) {
                int rb = wm * 32 + mi * 16;
                af[mi][0] = Ap[(rb + g    ) * 36 + kk + tg];
                af[mi][1] = Ap[(rb + 8 + g) * 36 + kk + tg];
                af[mi][2] = Ap[(rb + g    ) * 36 + kk + 4 + tg];
                af[mi][3] = Ap[(rb + 8 + g) * 36 + kk + 4 + tg];
            }
            #pragma unroll
            for (int ni = 0; ni < 4; ni++) {
                int cb = wn * 32 + ni * 8;
                bf[ni][0] = Bp[(kk + tg) * 72 + cb + g];
                bf[ni][1] = Bp[(kk + 4 + tg) * 72 + cb + g];
            }
            #pragma unroll
            for (int mi = 0; mi < 2; mi++)
                #pragma unroll
                for (int ni = 0; ni < 4; ni++)
                    MMA_TF32(acc[mi][ni],
                             af[mi][0], af[mi][1], af[mi][2], af[mi][3],
                             bf[ni][0], bf[ni][1]);
        }

        if (more) {
            stA(s ^ 1); stB(s ^ 1);
            __syncthreads();
        }
        s ^= 1;
    }

    #pragma unroll
    for (int mi = 0; mi < 2; mi++) {
        int r = row0 + wm * 32 + mi * 16 + g;
        #pragma unroll
        for (int ni = 0; ni < 4; ni++) {
            int c = col0 + wn * 32 + ni * 8 + 2 * tg;
            if (SPLITK) {
                float* p0 = Cb + (long long)r * ldc + c;
                atomicAdd(p0,                          acc[mi][ni][0]);
                atomicAdd(p0 + 1,                      acc[mi][ni][1]);
                atomicAdd(p0 + (long long)8 * ldc,     acc[mi][ni][2]);
                atomicAdd(p0 + (long long)8 * ldc + 1, acc[mi][ni][3]);
            } else {
                *reinterpret_cast<float2*>(Cb + (long long)r * ldc + c) =
                    make_float2(acc[mi][ni][0], acc[mi][ni][1]);
                *reinterpret_cast<float2*>(Cb + (long long)(r + 8) * ldc + c) =
                    make_float2(acc[mi][ni][2], acc[mi][ni][3]);
            }
        }
    }
}

// ---------------- elementwise / reductions ---------------------------------
__global__ void round_kernel(const float* __restrict__ src,
                             float* __restrict__ dst, int n4)
{
    int i = blockIdx.x * 256 + threadIdx.x;
    if (i >= n4) return;
    float4 v = reinterpret_cast<const float4*>(src)[i];
    v.x = rndtf(v.x); v.y = rndtf(v.y); v.z = rndtf(v.z); v.w = rndtf(v.w);
    reinterpret_cast<float4*>(dst)[i] = v;
}

__global__ void landmarks_kernel(const float* __restrict__ Q,
                                 const float* __restrict__ K,
                                 float* __restrict__ ql, float* __restrict__ kl)
{
    int i = blockIdx.x * 256 + threadIdx.x;
    int d = i & 63;
    int m = (i >> 6) & 255;
    int bh = i >> 14;
    long long base = ((long long)bh * 4096 + m * 16) * 64 + d;
    float sq = 0.f, sk = 0.f;
    #pragma unroll
    for (int j = 0; j < 16; j++) {
        sq += Q[base + j * 64];
        sk += K[base + j * 64];
    }
    ql[i] = rndtf(sq * 0.0625f);
    kl[i] = rndtf(sk * 0.0625f);
}

__global__ void softmax256_kernel(float* __restrict__ data, int rows)
{
    int gw   = (int)((blockIdx.x * (long long)blockDim.x + threadIdx.x) >> 5);
    int lane = threadIdx.x & 31;
    if (gw >= rows) return;
    float* p = data + (long long)gw * 256;
    float v[8];
    float mx = -1e30f;
    #pragma unroll
    for (int i = 0; i < 8; i++) { v[i] = p[lane + 32 * i]; mx = fmaxf(mx, v[i]); }
    #pragma unroll
    for (int o = 16; o > 0; o >>= 1) mx = fmaxf(mx, __shfl_xor_sync(0xffffffffu, mx, o));
    float s = 0.f;
    #pragma unroll
    for (int i = 0; i < 8; i++) { v[i] = expf(v[i] - mx); s += v[i]; }
    #pragma unroll
    for (int o = 16; o > 0; o >>= 1) s += __shfl_xor_sync(0xffffffffu, s, o);
    float inv = 1.f / s;
    #pragma unroll
    for (int i = 0; i < 8; i++) p[lane + 32 * i] = rndtf(v[i] * inv);
}

__global__ void softmax4096_kernel(float* __restrict__ data)
{
    float* p = data + (long long)blockIdx.x * 4096;
    int t = threadIdx.x;
    float v[16];
    float mx = -1e30f;
    #pragma unroll
    for (int i = 0; i < 16; i++) { v[i] = p[t + 256 * i]; mx = fmaxf(mx, v[i]); }
    __shared__ float red[256];
    red[t] = mx; __syncthreads();
    for (int s = 128; s > 0; s >>= 1) {
        if (t < s) red[t] = fmaxf(red[t], red[t + s]);
        __syncthreads();
    }
    mx = red[0]; __syncthreads();
    float sum = 0.f;
    #pragma unroll
    for (int i = 0; i < 16; i++) { v[i] = expf(v[i] - mx); sum += v[i]; }
    red[t] = sum; __syncthreads();
    for (int s = 128; s > 0; s >>= 1) {
        if (t < s) red[t] += red[t + s];
        __syncthreads();
    }
    float inv = 1.f / red[0];
    #pragma unroll
    for (int i = 0; i < 16; i++) p[t + 256 * i] = rndtf(v[i] * inv);
}

__global__ void mp_reset_kernel() { g_m1 = 0u; g_m2 = 0u; }

__global__ void mp_reduce_kernel(const float* __restrict__ a)
{
    int bh = blockIdx.x;
    int j  = threadIdx.x;
    const float* p = a + (long long)bh * 65536;
    float rs = 0.f, cs = 0.f;
    for (int i = 0; i < 256; i++) {
        rs += fabsf(p[j * 256 + i]);
        cs += fabsf(p[i * 256 + j]);
    }
    __shared__ float r1[256], r2[256];
    r1[j] = rs; r2[j] = cs; __syncthreads();
    for (int s = 128; s > 0; s >>= 1) {
        if (j < s) { r1[j] = fmaxf(r1[j], r1[j + s]); r2[j] = fmaxf(r2[j], r2[j + s]); }
        __syncthreads();
    }
    if (j == 0) {
        atomicMax(&g_m1, __float_as_uint(r1[0]));
        atomicMax(&g_m2, __float_as_uint(r2[0]));
    }
}

__global__ void mp_init_kernel(const float* __restrict__ a, float* __restrict__ z)
{
    long long i = (long long)blockIdx.x * 256 + threadIdx.x;
    int col = (int)(i & 255);
    int row = (int)((i >> 8) & 255);
    long long bh = i >> 16;
    float denom = __uint_as_float(g_m1) * __uint_as_float(g_m2);
    z[i] = rndtf(a[bh * 65536 + (long long)col * 256 + row] / denom);
}

// fused: depthwise residual conv (K=13, pad 6) + [b,h,n,d] -> [b,n,h*64+d]
__global__ void conv_tr_kernel(const float* __restrict__ src,
                               const float* __restrict__ w,
                               float* __restrict__ dst)
{
    long long o = (long long)blockIdx.x * 256 + threadIdx.x;
    int d = (int)(o & 63);
    int h = (int)((o >> 6) & 15);
    int n = (int)((o >> 10) & 4095);
    int b = (int)(o >> 22);
    long long s = (((long long)(b * 16 + h)) * 4096 + n) * 64 + d;
    float v = src[s];
    float r = 0.f;
    #pragma unroll
    for (int tt = 0; tt < 13; tt++) {
        int nn = n + tt - 6;
        if (nn >= 0 && nn < 4096)
            r += w[h * 13 + tt] * src[s + (long long)(tt - 6) * 64];
    }
    dst[o] = rndtf(v + r);
}

// ---------------- launch ----------------------------------------------------
static constexpr int SMEM1 = (2 * 4608 + 2 * 2304) * 4;  // 55296 (tgemm)

extern "C" void kernel_launch(void* const* d_in, const int* in_sizes, int n_in,
                              void* d_out, int out_size)
{
    (void)in_sizes; (void)n_in; (void)out_size;
    const float* x      = (const float*)d_in[0];
    const float* w_qkv  = (const float*)d_in[1];
    const float* w_conv = (const float*)d_in[2];
    const float* w_fc   = (const float*)d_in[3];
    const float* b_fc   = (const float*)d_in[4];
    float* dout = (float*)d_out;

    void* vp_;
    #define SYMP(nm) float* nm##_p; cudaGetSymbolAddress(&vp_, nm); nm##_p = (float*)vp_;
    SYMP(g_xr)   SYMP(g_wqkvr) SYMP(g_wfcr)
    SYMP(g_Q)    SYMP(g_K)    SYMP(g_V)
    SYMP(g_ql)   SYMP(g_kl)
    SYMP(g_attn1) SYMP(g_attn3) SYMP(g_attn2)
    SYMP(g_z0)   SYMP(g_z1)   SYMP(g_az)   SYMP(g_t2) SYMP(g_t4)
    SYMP(g_a3v)  SYMP(g_tmp2)
    SYMP(g_out)  SYMP(g_outT)
    #undef SYMP

    cudaFuncSetAttribute(tgemm3<false,false,false,true ,true >,
                         cudaFuncAttributeMaxDynamicSharedMemorySize, SMEM3);
    cudaFuncSetAttribute(tgemm3<true ,false,false,false,false>,
                         cudaFuncAttributeMaxDynamicSharedMemorySize, SMEM3);
    cudaFuncSetAttribute(tgemm3<false,false,false,false,true >,
                         cudaFuncAttributeMaxDynamicSharedMemorySize, SMEM3);
    cudaFuncSetAttribute(tgemm3<false,true ,false,false,true >,
                         cudaFuncAttributeMaxDynamicSharedMemorySize, SMEM3);
    cudaFuncSetAttribute(tgemm3<false,false,true ,false,false>,
                         cudaFuncAttributeMaxDynamicSharedMemorySize, SMEM3);
    cudaFuncSetAttribute(tgemm<false>,
                         cudaFuncAttributeMaxDynamicSharedMemorySize, SMEM1);
    cudaFuncSetAttribute(tgemm<true>,
                         cudaFuncAttributeMaxDynamicSharedMemorySize, SMEM1);

    // 0. pre-round external GEMM inputs to tf32
    round_kernel<<<16384, 256>>>(x, g_xr_p, 4194304);
    round_kernel<<<3072, 256>>>(w_qkv, g_wqkvr_p, 786432);
    round_kernel<<<1024, 256>>>(w_fc, g_wfcr_p, 262144);

    // 1. qkv projection fused with split+scale+round -> g_Q/g_K/g_V
    tgemm3<false,false,false,true,true><<<dim3(24, 128, 1), 128, SMEM3>>>(
        g_xr_p, g_wqkvr_p, nullptr, nullptr, 1024, 1024, 3072, 0, 0, 0, 0,
        0.f, 1.f, nullptr, g_Q_p, g_K_p, g_V_p);

    // 2. landmarks (rounded)
    landmarks_kernel<<<4096, 256>>>(g_Q_p, g_K_p, g_ql_p, g_kl_p);

    // 3. sim1 = Q @ kl^T   [4096,64]@[256,64]^T  (batch 64)
    tgemm3<true,false,false,false,false><<<dim3(2, 32, 64), 128, SMEM3>>>(
        g_Q_p, g_kl_p, g_attn1_p, nullptr, 64, 64, 64, 256,
        262144LL, 16384LL, 1048576LL, 0.f, 1.f, nullptr, nullptr, nullptr, nullptr);

    // 4. sim2 = ql @ kl^T  [256,64]@[256,64]^T
    tgemm3<true,false,false,false,false><<<dim3(2, 2, 64), 128, SMEM3>>>(
        g_ql_p, g_kl_p, g_attn2_p, nullptr, 64, 64, 64, 256,
        16384LL, 16384LL, 65536LL, 0.f, 1.f, nullptr, nullptr, nullptr, nullptr);

    // 5. sim3 = ql @ K^T   [256,64]@[4096,64]^T
    tgemm3<true,false,false,false,false><<<dim3(32, 2, 64), 128, SMEM3>>>(
        g_ql_p, g_K_p, g_attn3_p, nullptr, 64, 64, 64, 4096,
        16384LL, 262144LL, 1048576LL, 0.f, 1.f, nullptr, nullptr, nullptr, nullptr);

    // 6. softmaxes (in place, rounded)
    softmax256_kernel<<<32768, 256>>>(g_attn1_p, 262144);
    softmax256_kernel<<<2048, 256>>>(g_attn2_p, 16384);
    softmax4096_kernel<<<16384, 256>>>(g_attn3_p);

    // 7. MP init
    mp_reset_kernel<<<1, 1>>>();
    mp_reduce_kernel<<<64, 256>>>(g_attn2_p);
    mp_init_kernel<<<16384, 256>>>(g_attn2_p, g_z0_p);

    // 8. 6 Newton-Schulz iterations, epilogue-fused form:
    //    az = a@z;  t2 = 7az - az@az;  t4 = 15az - az@t2;  z' = (13z - z@t4)/4
    float* zin = g_z0_p; float* zout = g_z1_p;
    for (int it = 0; it < 6; it++) {
        tgemm3<false,false,false,false,true><<<dim3(2, 2, 64), 128, SMEM3>>>(
            g_attn2_p, zin, g_az_p, nullptr, 256, 256, 256, 256,
            65536LL, 65536LL, 65536LL, 0.f, 1.f, nullptr, nullptr, nullptr, nullptr);
        tgemm3<false,true,false,false,true><<<dim3(2, 2, 64), 128, SMEM3>>>(
            g_az_p, g_az_p, g_t2_p, g_az_p, 256, 256, 256, 256,
            65536LL, 65536LL, 65536LL, 7.f, 1.f, nullptr, nullptr, nullptr, nullptr);
        tgemm3<false,true,false,false,true><<<dim3(2, 2, 64), 128, SMEM3>>>(
            g_az_p, g_t2_p, g_t4_p, g_az_p, 256, 256, 256, 256,
            65536LL, 65536LL, 65536LL, 15.f, 1.f, nullptr, nullptr, nullptr, nullptr);
        tgemm3<false,true,false,false,true><<<dim3(2, 2, 64), 128, SMEM3>>>(
            zin, g_t4_p, zout, zin, 256, 256, 256, 256,
            65536LL, 65536LL, 65536LL, 13.f, 0.25f, nullptr, nullptr, nullptr, nullptr);
        float* tmp = zin; zin = zout; zout = tmp;
    }

    // 9. a3v = attn3 @ V  [256,4096]@[4096,64], split-K x8 atomic epilogue
    cudaMemsetAsync(g_a3v_p, 0, 1048576 * sizeof(float));
    tgemm<true><<<dim3(1, 2, 512), 256, SMEM1>>>(
        g_attn3_p, g_V_p, g_a3v_p, 512, 4096, 64, 64,
        1048576LL, 262144LL, 16384LL);

    // 10. tmp2 = z @ a3v   [256,256]@[256,64]
    tgemm<false><<<dim3(1, 2, 64), 256, SMEM1>>>(
        zin, g_a3v_p, g_tmp2_p, 256, 256, 64, 64,
        65536LL, 16384LL, 16384LL);

    // 11. out = attn1 @ tmp2   [4096,256]@[256,64]
    tgemm<false><<<dim3(1, 32, 64), 256, SMEM1>>>(
        g_attn1_p, g_tmp2_p, g_out_p, 256, 256, 64, 64,
        1048576LL, 16384LL, 262144LL);

    // 12. fused depthwise conv residual + transpose to [b,n,inner] (rounded)
    conv_tr_kernel<<<65536, 256>>>(g_out_p, w_conv, g_outT_p);

    // 13. final fc: d_out = outT @ w_fc + b_fc   [16384,1024]@[1024,1024]
    tgemm3<false,false,true,false,false><<<dim3(8, 128, 1), 128, SMEM3>>>(
        g_outT_p, g_wfcr_p, dout, nullptr, 1024, 1024, 1024, 1024,
        0, 0, 0, 0.f, 1.f, b_fc, nullptr, nullptr, nullptr);
}